// round 2
// baseline (speedup 1.0000x reference)
#include <cuda_runtime.h>

// Problem constants (shape-fixed per dataset)
#define NND 50000
#define NE  800000
#define HD  128
#define NL  4
#define EK  261   // 2*H + 1 + 4
#define NK  267   // H + H + 11
#define BE  64    // edges/nodes per block tile

// Scratch (no allocation allowed)
__device__ float g_radial[NE];
__device__ float g_agg[NND * HD];

__device__ __forceinline__ float silu_f(float v) {
    return __fdividef(v, 1.0f + __expf(-v));
}

// ---------------------------------------------------------------------------
// radial[e] = ||x[row]-x[col]||^2
// ---------------------------------------------------------------------------
__global__ void radial_kernel(const float* __restrict__ x, const int* __restrict__ ei, int E) {
    int e = blockIdx.x * blockDim.x + threadIdx.x;
    if (e >= E) return;
    int r = ei[e], c = ei[E + e];
    float dx = x[r * 3 + 0] - x[c * 3 + 0];
    float dy = x[r * 3 + 1] - x[c * 3 + 1];
    float dz = x[r * 3 + 2] - x[c * 3 + 2];
    g_radial[e] = dx * dx + dy * dy + dz * dz;
}

// ---------------------------------------------------------------------------
// h = h0 @ emb_w + emb_b   (one block per node, 128 threads)
// ---------------------------------------------------------------------------
__global__ void embed_kernel(const float* __restrict__ h0, const float* __restrict__ w,
                             const float* __restrict__ b, float* __restrict__ h) {
    __shared__ float s[11];
    int n = blockIdx.x;
    int f = threadIdx.x;
    if (f < 11) s[f] = h0[n * 11 + f];
    __syncthreads();
    float acc = b[f];
#pragma unroll
    for (int k = 0; k < 11; k++) acc += s[k] * w[k * HD + f];
    h[n * HD + f] = acc;
}

__global__ void zero_agg_kernel(int n4) {
    int i = blockIdx.x * blockDim.x + threadIdx.x;
    if (i < n4) reinterpret_cast<float4*>(g_agg)[i] = make_float4(0.f, 0.f, 0.f, 0.f);
}

// ---------------------------------------------------------------------------
// Fused edge model: gather -> GEMM(261x128) -> silu -> GEMM(128x128) -> silu
//                   -> *edge_mask -> atomic scatter into g_agg
// Block: 256 threads, BE=64 edges. Thread computes 8 edges x 4 features.
// smem: As[BE][EK] (odd stride -> conflict free) | Ws[32][128] | idx/mask arrays
// ---------------------------------------------------------------------------
__global__ void edge_kernel(const float* __restrict__ h,
                            const float* __restrict__ edge_attr,
                            const float* __restrict__ edge_mask,
                            const int* __restrict__ ei,
                            const float* __restrict__ W1, const float* __restrict__ b1,
                            const float* __restrict__ W2, const float* __restrict__ b2,
                            int E) {
    extern __shared__ float sm[];
    float* As = sm;                       // BE*EK
    float* Ws = sm + BE * EK;             // 32*HD
    int*   rs = (int*)(Ws + 32 * HD);     // BE
    int*   cs = rs + BE;                  // BE
    float* ms = (float*)(cs + BE);        // BE

    int tid = threadIdx.x;
    int e0 = blockIdx.x * BE;

    if (tid < BE) {
        int ge = e0 + tid;
        int r = 0, c = 0; float mk = 0.f;
        if (ge < E) { r = ei[ge]; c = ei[E + ge]; mk = edge_mask[ge]; }
        rs[tid] = r; cs[tid] = c; ms[tid] = mk;
    }
    __syncthreads();

    // Gather A = [h_row | h_col | radial | edge_attr]
    for (int idx = tid; idx < BE * EK; idx += 256) {
        int e = idx / EK;
        int k = idx - e * EK;
        int ge = e0 + e;
        float v = 0.f;
        if (ge < E) {
            if (k < HD)            v = h[rs[e] * HD + k];
            else if (k < 2 * HD)   v = h[cs[e] * HD + (k - HD)];
            else if (k == 2 * HD)  v = g_radial[ge];
            else                   v = edge_attr[ge * 4 + (k - 2 * HD - 1)];
        }
        As[e * EK + k] = v;
    }
    __syncthreads();

    int tx = tid & 31;      // feature group base
    int ty = tid >> 5;      // edge group base (0..7)

    // ---- GEMM1 ----
    float c1[8][4];
#pragma unroll
    for (int j = 0; j < 4; j++) {
        float bv = b1[tx + 32 * j];
#pragma unroll
        for (int i = 0; i < 8; i++) c1[i][j] = bv;
    }
    for (int k0 = 0; k0 < EK; k0 += 32) {
        int kc = min(32, EK - k0);
        __syncthreads();
        for (int idx = tid; idx < kc * HD; idx += 256)
            Ws[idx] = W1[(k0 + (idx >> 7)) * HD + (idx & (HD - 1))];
        __syncthreads();
#pragma unroll 4
        for (int kk = 0; kk < kc; kk++) {
            float w0 = Ws[kk * HD + tx];
            float w1 = Ws[kk * HD + tx + 32];
            float w2 = Ws[kk * HD + tx + 64];
            float w3 = Ws[kk * HD + tx + 96];
#pragma unroll
            for (int i = 0; i < 8; i++) {
                float a = As[(ty + 8 * i) * EK + k0 + kk];
                c1[i][0] += a * w0; c1[i][1] += a * w1;
                c1[i][2] += a * w2; c1[i][3] += a * w3;
            }
        }
    }
    __syncthreads();   // all As reads done; reuse region for m1

    float* M1 = As;    // stride HD
#pragma unroll
    for (int i = 0; i < 8; i++)
#pragma unroll
        for (int j = 0; j < 4; j++)
            M1[(ty + 8 * i) * HD + tx + 32 * j] = silu_f(c1[i][j]);
    __syncthreads();

    // ---- GEMM2 ----
    float c2[8][4];
#pragma unroll
    for (int j = 0; j < 4; j++) {
        float bv = b2[tx + 32 * j];
#pragma unroll
        for (int i = 0; i < 8; i++) c2[i][j] = bv;
    }
    for (int k0 = 0; k0 < HD; k0 += 32) {
        __syncthreads();
        for (int idx = tid; idx < 32 * HD; idx += 256)
            Ws[idx] = W2[(k0 + (idx >> 7)) * HD + (idx & (HD - 1))];
        __syncthreads();
#pragma unroll 4
        for (int kk = 0; kk < 32; kk++) {
            float w0 = Ws[kk * HD + tx];
            float w1 = Ws[kk * HD + tx + 32];
            float w2 = Ws[kk * HD + tx + 64];
            float w3 = Ws[kk * HD + tx + 96];
#pragma unroll
            for (int i = 0; i < 8; i++) {
                float a = M1[(ty + 8 * i) * HD + k0 + kk];
                c2[i][0] += a * w0; c2[i][1] += a * w1;
                c2[i][2] += a * w2; c2[i][3] += a * w3;
            }
        }
    }

    // silu + mask + scatter
#pragma unroll
    for (int i = 0; i < 8; i++) {
        int e = ty + 8 * i;
        int ge = e0 + e;
        if (ge < E) {
            float mk = ms[e];
            int base = rs[e] * HD;
#pragma unroll
            for (int j = 0; j < 4; j++) {
                float m = silu_f(c2[i][j]) * mk;
                atomicAdd(&g_agg[base + tx + 32 * j], m);
            }
        }
    }
}

// ---------------------------------------------------------------------------
// Fused node model: A=[h | agg | h0] -> GEMM(267x128) -> silu -> GEMM(128x128)
//                   -> h += out   (in place on d_out)
// ---------------------------------------------------------------------------
__global__ void node_kernel(float* __restrict__ h, const float* __restrict__ h0,
                            const float* __restrict__ W1, const float* __restrict__ b1,
                            const float* __restrict__ W2, const float* __restrict__ b2,
                            int N) {
    extern __shared__ float sm[];
    float* As = sm;                  // BE*NK
    float* Ws = sm + BE * NK;        // 32*HD

    int tid = threadIdx.x;
    int n0 = blockIdx.x * BE;

    for (int idx = tid; idx < BE * NK; idx += 256) {
        int e = idx / NK;
        int k = idx - e * NK;
        int gn = n0 + e;
        float v = 0.f;
        if (gn < N) {
            if (k < HD)           v = h[gn * HD + k];
            else if (k < 2 * HD)  v = g_agg[gn * HD + (k - HD)];
            else                  v = h0[gn * 11 + (k - 2 * HD)];
        }
        As[e * NK + k] = v;
    }
    __syncthreads();

    int tx = tid & 31;
    int ty = tid >> 5;

    float c1[8][4];
#pragma unroll
    for (int j = 0; j < 4; j++) {
        float bv = b1[tx + 32 * j];
#pragma unroll
        for (int i = 0; i < 8; i++) c1[i][j] = bv;
    }
    for (int k0 = 0; k0 < NK; k0 += 32) {
        int kc = min(32, NK - k0);
        __syncthreads();
        for (int idx = tid; idx < kc * HD; idx += 256)
            Ws[idx] = W1[(k0 + (idx >> 7)) * HD + (idx & (HD - 1))];
        __syncthreads();
#pragma unroll 4
        for (int kk = 0; kk < kc; kk++) {
            float w0 = Ws[kk * HD + tx];
            float w1 = Ws[kk * HD + tx + 32];
            float w2 = Ws[kk * HD + tx + 64];
            float w3 = Ws[kk * HD + tx + 96];
#pragma unroll
            for (int i = 0; i < 8; i++) {
                float a = As[(ty + 8 * i) * NK + k0 + kk];
                c1[i][0] += a * w0; c1[i][1] += a * w1;
                c1[i][2] += a * w2; c1[i][3] += a * w3;
            }
        }
    }
    __syncthreads();

    float* M1 = As;   // stride HD
#pragma unroll
    for (int i = 0; i < 8; i++)
#pragma unroll
        for (int j = 0; j < 4; j++)
            M1[(ty + 8 * i) * HD + tx + 32 * j] = silu_f(c1[i][j]);
    __syncthreads();

    float c2[8][4];
#pragma unroll
    for (int j = 0; j < 4; j++) {
        float bv = b2[tx + 32 * j];
#pragma unroll
        for (int i = 0; i < 8; i++) c2[i][j] = bv;
    }
    for (int k0 = 0; k0 < HD; k0 += 32) {
        __syncthreads();
        for (int idx = tid; idx < 32 * HD; idx += 256)
            Ws[idx] = W2[(k0 + (idx >> 7)) * HD + (idx & (HD - 1))];
        __syncthreads();
#pragma unroll 4
        for (int kk = 0; kk < 32; kk++) {
            float w0 = Ws[kk * HD + tx];
            float w1 = Ws[kk * HD + tx + 32];
            float w2 = Ws[kk * HD + tx + 64];
            float w3 = Ws[kk * HD + tx + 96];
#pragma unroll
            for (int i = 0; i < 8; i++) {
                float a = M1[(ty + 8 * i) * HD + k0 + kk];
                c2[i][0] += a * w0; c2[i][1] += a * w1;
                c2[i][2] += a * w2; c2[i][3] += a * w3;
            }
        }
    }

    // h += out (no second silu in node model)
#pragma unroll
    for (int i = 0; i < 8; i++) {
        int gn = n0 + ty + 8 * i;
        if (gn < N) {
#pragma unroll
            for (int j = 0; j < 4; j++) {
                int o = gn * HD + tx + 32 * j;
                h[o] = h[o] + c2[i][j];
            }
        }
    }
}

// ---------------------------------------------------------------------------
extern "C" void kernel_launch(void* const* d_in, const int* in_sizes, int n_in,
                              void* d_out, int out_size) {
    const float* h0        = (const float*)d_in[0];
    const float* x         = (const float*)d_in[1];
    const int*   ei        = (const int*)  d_in[2];
    const float* edge_attr = (const float*)d_in[3];
    // d_in[4] node_mask: unused by reference
    const float* edge_mask = (const float*)d_in[5];

    // n_nodes scalar may or may not be present in the input list; detect via size
    int wi = (in_sizes[6] == 1) ? 7 : 6;
    const float* emb_w = (const float*)d_in[wi + 0];
    const float* emb_b = (const float*)d_in[wi + 1];
    const float* ew1   = (const float*)d_in[wi + 2];
    const float* eb1   = (const float*)d_in[wi + 3];
    const float* ew2   = (const float*)d_in[wi + 4];
    const float* eb2   = (const float*)d_in[wi + 5];
    const float* nw1   = (const float*)d_in[wi + 6];
    const float* nb1   = (const float*)d_in[wi + 7];
    const float* nw2   = (const float*)d_in[wi + 8];
    const float* nb2   = (const float*)d_in[wi + 9];

    float* h = (float*)d_out;
    int N = in_sizes[0] / 11;
    int E = in_sizes[3] / 4;

    const int EDGE_SMEM = (BE * EK + 32 * HD) * 4 + BE * 12;   // As + Ws + rs/cs/ms
    const int NODE_SMEM = (BE * NK + 32 * HD) * 4;

    cudaFuncSetAttribute(edge_kernel, cudaFuncAttributeMaxDynamicSharedMemorySize, EDGE_SMEM);
    cudaFuncSetAttribute(node_kernel, cudaFuncAttributeMaxDynamicSharedMemorySize, NODE_SMEM);

    radial_kernel<<<(E + 255) / 256, 256>>>(x, ei, E);
    embed_kernel<<<N, HD>>>(h0, emb_w, emb_b, h);

    int n4 = (N * HD) / 4;
    int eblocks = (E + BE - 1) / BE;
    int nblocks = (N + BE - 1) / BE;

    for (int l = 0; l < NL; l++) {
        zero_agg_kernel<<<(n4 + 255) / 256, 256>>>(n4);
        edge_kernel<<<eblocks, 256, EDGE_SMEM>>>(h, edge_attr, edge_mask, ei,
                                                 ew1 + l * EK * HD, eb1 + l * HD,
                                                 ew2 + l * HD * HD, eb2 + l * HD, E);
        node_kernel<<<nblocks, 256, NODE_SMEM>>>(h, h0,
                                                 nw1 + l * NK * HD, nb1 + l * HD,
                                                 nw2 + l * HD * HD, nb2 + l * HD, N);
    }
}

// round 4
// speedup vs baseline: 1.5252x; 1.5252x over previous
#include <cuda_runtime.h>
#include <cstdint>

#define HD  128
#define NL  4
#define NKC 267      // node concat width
#define BM  128      // edges per block
#define BEN 64       // nodes per block (node kernel)

__device__ float g_radial[800000];
__device__ float g_agg[50000 * HD];

__device__ __forceinline__ float silu_f(float v) {
    return __fdividef(v, 1.0f + __expf(-v));
}

// fp32 -> tf32 bits (round to nearest)
__device__ __forceinline__ uint32_t f2tf(float f) {
    uint32_t r;
    asm("cvt.rna.tf32.f32 %0, %1;" : "=r"(r) : "f"(f));
    return r;
}

// warp mma: D(16x8) += A(16x8) * B(8x8), tf32 in, f32 acc
__device__ __forceinline__ void mma8(float* d, const uint32_t* a, const uint32_t* b) {
    asm volatile(
        "mma.sync.aligned.m16n8k8.row.col.f32.tf32.tf32.f32 "
        "{%0,%1,%2,%3}, {%4,%5,%6,%7}, {%8,%9}, {%0,%1,%2,%3};"
        : "+f"(d[0]), "+f"(d[1]), "+f"(d[2]), "+f"(d[3])
        : "r"(a[0]), "r"(a[1]), "r"(a[2]), "r"(a[3]), "r"(b[0]), "r"(b[1]));
}

// ---------------------------------------------------------------------------
__global__ void radial_kernel(const float* __restrict__ x, const int* __restrict__ ei, int E) {
    int e = blockIdx.x * blockDim.x + threadIdx.x;
    if (e >= E) return;
    int r = ei[e], c = ei[E + e];
    float dx = x[r * 3 + 0] - x[c * 3 + 0];
    float dy = x[r * 3 + 1] - x[c * 3 + 1];
    float dz = x[r * 3 + 2] - x[c * 3 + 2];
    g_radial[e] = dx * dx + dy * dy + dz * dz;
}

__global__ void embed_kernel(const float* __restrict__ h0, const float* __restrict__ w,
                             const float* __restrict__ b, float* __restrict__ h) {
    __shared__ float s[11];
    int n = blockIdx.x;
    int f = threadIdx.x;
    if (f < 11) s[f] = h0[n * 11 + f];
    __syncthreads();
    float acc = b[f];
#pragma unroll
    for (int k = 0; k < 11; k++) acc += s[k] * w[k * HD + f];
    h[n * HD + f] = acc;
}

__global__ void zero_agg_kernel(int n4) {
    int i = blockIdx.x * blockDim.x + threadIdx.x;
    if (i < n4) reinterpret_cast<float4*>(g_agg)[i] = make_float4(0.f, 0.f, 0.f, 0.f);
}

// ---------------------------------------------------------------------------
// Edge model on tensor cores (mma.sync tf32).
// Block: 128 threads (4 warps), 128 edges x 128 out. Warp tile 64x64.
// GEMM1 K=264 (3 chunks of 88), GEMM2 K=128 (single pass).
// ---------------------------------------------------------------------------
#define SA  92    // GEMM1 smem k-stride (mod 8 == 4 -> conflict-free frags)
#define S2  132   // GEMM2 smem k-stride
#define SO_RS 0
#define SO_CS 512
#define SO_MS 1024
#define SO_B1 1536
#define SO_B2 2048
#define SO_A  2560
#define SO_B  (2560 + 67584)
#define SMEM_EDGE (2560 + 2 * 67584)

__global__ void __launch_bounds__(128, 1) edge_mma_kernel(
    const float* __restrict__ h, const float* __restrict__ edge_attr,
    const float* __restrict__ edge_mask, const int* __restrict__ ei,
    const float* __restrict__ W1, const float* __restrict__ b1,
    const float* __restrict__ W2, const float* __restrict__ b2, int E) {
    extern __shared__ char sm[];
    int*      rs  = (int*)(sm + SO_RS);
    int*      cs  = (int*)(sm + SO_CS);
    float*    ms  = (float*)(sm + SO_MS);
    float*    b1s = (float*)(sm + SO_B1);
    float*    b2s = (float*)(sm + SO_B2);
    uint32_t* As  = (uint32_t*)(sm + SO_A);
    uint32_t* Bs  = (uint32_t*)(sm + SO_B);

    int tid = threadIdx.x;
    int e0 = blockIdx.x * BM;
    {
        int ge = e0 + tid;
        int r = 0, c = 0; float mk = 0.f;
        if (ge < E) { r = ei[ge]; c = ei[E + ge]; mk = edge_mask[ge]; }
        rs[tid] = r; cs[tid] = c; ms[tid] = mk;
        b1s[tid] = b1[tid]; b2s[tid] = b2[tid];
    }
    __syncthreads();

    int lane = tid & 31, wid = tid >> 5;
    int g = lane >> 2, tg = lane & 3;
    int wm = wid >> 1, wn = wid & 1;

    float acc[4][8][4];
#pragma unroll
    for (int mt = 0; mt < 4; mt++)
#pragma unroll
        for (int nt = 0; nt < 8; nt++)
#pragma unroll
            for (int q = 0; q < 4; q++) acc[mt][nt][q] = 0.f;

    // per-thread row sources for staging (thread == row)
    const float* hrp = h + (size_t)rs[tid] * HD;
    const float* hcp = h + (size_t)cs[tid] * HD;
    int ge = e0 + tid;
    int gec = (ge < E) ? ge : 0;
    float rad = g_radial[gec];
    float4 ea = *(const float4*)(edge_attr + (size_t)gec * 4);

    // ---- GEMM1: 3 chunks of K=88 ----
    for (int ck = 0; ck < 3; ck++) {
        __syncthreads();
        {   // A chunk: [128 rows][88 k] tf32, row = tid
            uint32_t* dst = As + tid * SA;
#pragma unroll
            for (int j = 0; j < 22; j++) {
                int kg = ck * 88 + j * 4;
                float4 v;
                if (kg < 128)       v = *(const float4*)(hrp + kg);
                else if (kg < 256)  v = *(const float4*)(hcp + (kg - 128));
                else if (kg == 256) v = make_float4(rad, ea.x, ea.y, ea.z);
                else                v = make_float4(ea.w, 0.f, 0.f, 0.f);
                dst[j * 4 + 0] = f2tf(v.x);
                dst[j * 4 + 1] = f2tf(v.y);
                dst[j * 4 + 2] = f2tf(v.z);
                dst[j * 4 + 3] = f2tf(v.w);
            }
        }
        // B chunk: W1^T -> [128 n][88 k]
        for (int idx = tid; idx < 88 * 32; idx += 128) {
            int kk = idx >> 5;
            int n0 = (idx & 31) << 2;
            int kg = ck * 88 + kk;
            float4 v = make_float4(0.f, 0.f, 0.f, 0.f);
            if (kg < 261) v = *(const float4*)(W1 + (size_t)kg * HD + n0);
            Bs[(n0 + 0) * SA + kk] = f2tf(v.x);
            Bs[(n0 + 1) * SA + kk] = f2tf(v.y);
            Bs[(n0 + 2) * SA + kk] = f2tf(v.z);
            Bs[(n0 + 3) * SA + kk] = f2tf(v.w);
        }
        __syncthreads();

#pragma unroll 1
        for (int kc = 0; kc < 11; kc++) {
            int kb = kc * 8;
            uint32_t a[4][4];
#pragma unroll
            for (int mt = 0; mt < 4; mt++) {
                int r0 = wm * 64 + mt * 16 + g;
                a[mt][0] = As[r0 * SA + kb + tg];
                a[mt][1] = As[(r0 + 8) * SA + kb + tg];
                a[mt][2] = As[r0 * SA + kb + tg + 4];
                a[mt][3] = As[(r0 + 8) * SA + kb + tg + 4];
            }
#pragma unroll
            for (int nt = 0; nt < 8; nt++) {
                int cc = wn * 64 + nt * 8 + g;
                uint32_t b[2];
                b[0] = Bs[cc * SA + kb + tg];
                b[1] = Bs[cc * SA + kb + tg + 4];
#pragma unroll
                for (int mt = 0; mt < 4; mt++) mma8(acc[mt][nt], a[mt], b);
            }
        }
    }
    __syncthreads();

    // ---- epilogue 1: m1 = tf32(silu(acc + b1)) -> As (stride S2); stage W2^T ----
#pragma unroll
    for (int mt = 0; mt < 4; mt++) {
#pragma unroll
        for (int nt = 0; nt < 8; nt++) {
            int col = wn * 64 + nt * 8 + 2 * tg;
            int r0  = wm * 64 + mt * 16 + g;
            float bb0 = b1s[col], bb1 = b1s[col + 1];
            As[r0 * S2 + col]           = f2tf(silu_f(acc[mt][nt][0] + bb0));
            As[r0 * S2 + col + 1]       = f2tf(silu_f(acc[mt][nt][1] + bb1));
            As[(r0 + 8) * S2 + col]     = f2tf(silu_f(acc[mt][nt][2] + bb0));
            As[(r0 + 8) * S2 + col + 1] = f2tf(silu_f(acc[mt][nt][3] + bb1));
        }
    }
    for (int idx = tid; idx < 128 * 32; idx += 128) {
        int kk = idx >> 5;
        int n0 = (idx & 31) << 2;
        float4 v = *(const float4*)(W2 + (size_t)kk * HD + n0);
        Bs[(n0 + 0) * S2 + kk] = f2tf(v.x);
        Bs[(n0 + 1) * S2 + kk] = f2tf(v.y);
        Bs[(n0 + 2) * S2 + kk] = f2tf(v.z);
        Bs[(n0 + 3) * S2 + kk] = f2tf(v.w);
    }
#pragma unroll
    for (int mt = 0; mt < 4; mt++)
#pragma unroll
        for (int nt = 0; nt < 8; nt++)
#pragma unroll
            for (int q = 0; q < 4; q++) acc[mt][nt][q] = 0.f;
    __syncthreads();

    // ---- GEMM2: K=128 ----
#pragma unroll 1
    for (int kc = 0; kc < 16; kc++) {
        int kb = kc * 8;
        uint32_t a[4][4];
#pragma unroll
        for (int mt = 0; mt < 4; mt++) {
            int r0 = wm * 64 + mt * 16 + g;
            a[mt][0] = As[r0 * S2 + kb + tg];
            a[mt][1] = As[(r0 + 8) * S2 + kb + tg];
            a[mt][2] = As[r0 * S2 + kb + tg + 4];
            a[mt][3] = As[(r0 + 8) * S2 + kb + tg + 4];
        }
#pragma unroll
        for (int nt = 0; nt < 8; nt++) {
            int cc = wn * 64 + nt * 8 + g;
            uint32_t b[2];
            b[0] = Bs[cc * S2 + kb + tg];
            b[1] = Bs[cc * S2 + kb + tg + 4];
#pragma unroll
            for (int mt = 0; mt < 4; mt++) mma8(acc[mt][nt], a[mt], b);
        }
    }

    // ---- epilogue 2: silu(+b2) * mask, atomic scatter ----
#pragma unroll
    for (int mt = 0; mt < 4; mt++) {
#pragma unroll
        for (int nt = 0; nt < 8; nt++) {
            int col = wn * 64 + nt * 8 + 2 * tg;
            int r0  = wm * 64 + mt * 16 + g;
            int r1  = r0 + 8;
            float bb0 = b2s[col], bb1 = b2s[col + 1];
            if (e0 + r0 < E) {
                float mk = ms[r0];
                int base = rs[r0] * HD;
                atomicAdd(&g_agg[base + col],     silu_f(acc[mt][nt][0] + bb0) * mk);
                atomicAdd(&g_agg[base + col + 1], silu_f(acc[mt][nt][1] + bb1) * mk);
            }
            if (e0 + r1 < E) {
                float mk = ms[r1];
                int base = rs[r1] * HD;
                atomicAdd(&g_agg[base + col],     silu_f(acc[mt][nt][2] + bb0) * mk);
                atomicAdd(&g_agg[base + col + 1], silu_f(acc[mt][nt][3] + bb1) * mk);
            }
        }
    }
}

// ---------------------------------------------------------------------------
// Node model (FFMA path, unchanged)
// ---------------------------------------------------------------------------
__global__ void node_kernel(float* __restrict__ h, const float* __restrict__ h0,
                            const float* __restrict__ W1, const float* __restrict__ b1,
                            const float* __restrict__ W2, const float* __restrict__ b2,
                            int N) {
    extern __shared__ float smf[];
    float* As = smf;
    float* Ws = smf + BEN * NKC;

    int tid = threadIdx.x;
    int n0 = blockIdx.x * BEN;

    for (int idx = tid; idx < BEN * NKC; idx += 256) {
        int e = idx / NKC;
        int k = idx - e * NKC;
        int gn = n0 + e;
        float v = 0.f;
        if (gn < N) {
            if (k < HD)           v = h[gn * HD + k];
            else if (k < 2 * HD)  v = g_agg[gn * HD + (k - HD)];
            else                  v = h0[gn * 11 + (k - 2 * HD)];
        }
        As[e * NKC + k] = v;
    }
    __syncthreads();

    int tx = tid & 31;
    int ty = tid >> 5;

    float c1[8][4];
#pragma unroll
    for (int j = 0; j < 4; j++) {
        float bv = b1[tx + 32 * j];
#pragma unroll
        for (int i = 0; i < 8; i++) c1[i][j] = bv;
    }
    for (int k0 = 0; k0 < NKC; k0 += 32) {
        int kc = min(32, NKC - k0);
        __syncthreads();
        for (int idx = tid; idx < kc * HD; idx += 256)
            Ws[idx] = W1[(k0 + (idx >> 7)) * HD + (idx & (HD - 1))];
        __syncthreads();
#pragma unroll 4
        for (int kk = 0; kk < kc; kk++) {
            float w0 = Ws[kk * HD + tx];
            float w1 = Ws[kk * HD + tx + 32];
            float w2 = Ws[kk * HD + tx + 64];
            float w3 = Ws[kk * HD + tx + 96];
#pragma unroll
            for (int i = 0; i < 8; i++) {
                float a = As[(ty + 8 * i) * NKC + k0 + kk];
                c1[i][0] += a * w0; c1[i][1] += a * w1;
                c1[i][2] += a * w2; c1[i][3] += a * w3;
            }
        }
    }
    __syncthreads();

    float* M1 = As;
#pragma unroll
    for (int i = 0; i < 8; i++)
#pragma unroll
        for (int j = 0; j < 4; j++)
            M1[(ty + 8 * i) * HD + tx + 32 * j] = silu_f(c1[i][j]);
    __syncthreads();

    float c2[8][4];
#pragma unroll
    for (int j = 0; j < 4; j++) {
        float bv = b2[tx + 32 * j];
#pragma unroll
        for (int i = 0; i < 8; i++) c2[i][j] = bv;
    }
    for (int k0 = 0; k0 < HD; k0 += 32) {
        __syncthreads();
        for (int idx = tid; idx < 32 * HD; idx += 256)
            Ws[idx] = W2[(k0 + (idx >> 7)) * HD + (idx & (HD - 1))];
        __syncthreads();
#pragma unroll 4
        for (int kk = 0; kk < 32; kk++) {
            float w0 = Ws[kk * HD + tx];
            float w1 = Ws[kk * HD + tx + 32];
            float w2 = Ws[kk * HD + tx + 64];
            float w3 = Ws[kk * HD + tx + 96];
#pragma unroll
            for (int i = 0; i < 8; i++) {
                float a = M1[(ty + 8 * i) * HD + k0 + kk];
                c2[i][0] += a * w0; c2[i][1] += a * w1;
                c2[i][2] += a * w2; c2[i][3] += a * w3;
            }
        }
    }

#pragma unroll
    for (int i = 0; i < 8; i++) {
        int gn = n0 + ty + 8 * i;
        if (gn < N) {
#pragma unroll
            for (int j = 0; j < 4; j++) {
                int o = gn * HD + tx + 32 * j;
                h[o] = h[o] + c2[i][j];
            }
        }
    }
}

// ---------------------------------------------------------------------------
extern "C" void kernel_launch(void* const* d_in, const int* in_sizes, int n_in,
                              void* d_out, int out_size) {
    const float* h0        = (const float*)d_in[0];
    const float* x         = (const float*)d_in[1];
    const int*   ei        = (const int*)  d_in[2];
    const float* edge_attr = (const float*)d_in[3];
    const float* edge_mask = (const float*)d_in[5];

    int wi = (in_sizes[6] == 1) ? 7 : 6;
    const float* emb_w = (const float*)d_in[wi + 0];
    const float* emb_b = (const float*)d_in[wi + 1];
    const float* ew1   = (const float*)d_in[wi + 2];
    const float* eb1   = (const float*)d_in[wi + 3];
    const float* ew2   = (const float*)d_in[wi + 4];
    const float* eb2   = (const float*)d_in[wi + 5];
    const float* nw1   = (const float*)d_in[wi + 6];
    const float* nb1   = (const float*)d_in[wi + 7];
    const float* nw2   = (const float*)d_in[wi + 8];
    const float* nb2   = (const float*)d_in[wi + 9];

    float* h = (float*)d_out;
    int N = in_sizes[0] / 11;
    int E = in_sizes[3] / 4;

    const int NODE_SMEM = (BEN * NKC + 32 * HD) * 4;
    cudaFuncSetAttribute(edge_mma_kernel, cudaFuncAttributeMaxDynamicSharedMemorySize, SMEM_EDGE);
    cudaFuncSetAttribute(node_kernel, cudaFuncAttributeMaxDynamicSharedMemorySize, NODE_SMEM);

    radial_kernel<<<(E + 255) / 256, 256>>>(x, ei, E);
    embed_kernel<<<N, HD>>>(h0, emb_w, emb_b, h);

    int n4 = (N * HD) / 4;
    int eblocks = (E + BM - 1) / BM;
    int nblocks = (N + BEN - 1) / BEN;

    for (int l = 0; l < NL; l++) {
        zero_agg_kernel<<<(n4 + 255) / 256, 256>>>(n4);
        edge_mma_kernel<<<eblocks, 128, SMEM_EDGE>>>(h, edge_attr, edge_mask, ei,
                                                     ew1 + (size_t)l * 261 * HD, eb1 + l * HD,
                                                     ew2 + (size_t)l * HD * HD, eb2 + l * HD, E);
        node_kernel<<<nblocks, 256, NODE_SMEM>>>(h, h0,
                                                 nw1 + (size_t)l * NKC * HD, nb1 + l * HD,
                                                 nw2 + (size_t)l * HD * HD, nb2 + l * HD, N);
    }
}

// round 7
// speedup vs baseline: 3.1911x; 2.0923x over previous
#include <cuda_runtime.h>
#include <cstdint>

#define HD  128
#define NL  4
#define NKC 267
#define BM  128
#define BEN 64
#define S2  132   // smem k-stride (words): conflict-free frag reads

__device__ float g_radial[800000];
__device__ float g_agg[50000 * HD];
__device__ float g_Pa[50000 * HD];
__device__ float g_Pb[50000 * HD];

__device__ __forceinline__ float silu_f(float v) {
    return __fdividef(v, 1.0f + __expf(-v));
}
__device__ __forceinline__ uint32_t f2tf(float f) {
    uint32_t r;
    asm("cvt.rna.tf32.f32 %0, %1;" : "=r"(r) : "f"(f));
    return r;
}
__device__ __forceinline__ void mma8(float* d, const uint32_t* a, const uint32_t* b) {
    asm volatile(
        "mma.sync.aligned.m16n8k8.row.col.f32.tf32.tf32.f32 "
        "{%0,%1,%2,%3}, {%4,%5,%6,%7}, {%8,%9}, {%0,%1,%2,%3};"
        : "+f"(d[0]), "+f"(d[1]), "+f"(d[2]), "+f"(d[3])
        : "r"(a[0]), "r"(a[1]), "r"(a[2]), "r"(a[3]), "r"(b[0]), "r"(b[1]));
}

// ---------------------------------------------------------------------------
__global__ void radial_kernel(const float* __restrict__ x, const int* __restrict__ ei, int E) {
    int e = blockIdx.x * blockDim.x + threadIdx.x;
    if (e >= E) return;
    int r = ei[e], c = ei[E + e];
    float dx = x[r * 3 + 0] - x[c * 3 + 0];
    float dy = x[r * 3 + 1] - x[c * 3 + 1];
    float dz = x[r * 3 + 2] - x[c * 3 + 2];
    g_radial[e] = dx * dx + dy * dy + dz * dz;
}

__global__ void embed_kernel(const float* __restrict__ h0, const float* __restrict__ w,
                             const float* __restrict__ b, float* __restrict__ h) {
    __shared__ float s[11];
    int n = blockIdx.x;
    int f = threadIdx.x;
    if (f < 11) s[f] = h0[n * 11 + f];
    __syncthreads();
    float acc = b[f];
#pragma unroll
    for (int k = 0; k < 11; k++) acc += s[k] * w[k * HD + f];
    h[n * HD + f] = acc;
}

__global__ void zero_agg_kernel(int n4) {
    int i = blockIdx.x * blockDim.x + threadIdx.x;
    if (i < n4) reinterpret_cast<float4*>(g_agg)[i] = make_float4(0.f, 0.f, 0.f, 0.f);
}

// ---------------------------------------------------------------------------
// proj: Pa = h @ W1[0:128] + b1 ; Pb = h @ W1[128:256]
// 256 threads / 8 warps, 128 rows per block, warp tile 64x32.
// ---------------------------------------------------------------------------
#define PROJ_SMEM (512 + 2 * 67584)
__global__ void __launch_bounds__(256, 1) proj_kernel(
    const float* __restrict__ h, const float* __restrict__ W1,
    const float* __restrict__ b1, int N) {
    extern __shared__ char sm[];
    float*    b1s = (float*)sm;
    uint32_t* As  = (uint32_t*)(sm + 512);
    uint32_t* Bs  = (uint32_t*)(sm + 512 + 67584);

    int tid = threadIdx.x;
    int r0 = blockIdx.x * 128;
    if (tid < 128) b1s[tid] = b1[tid];

    // stage A = tf32(h rows)
    for (int idx = tid; idx < 4096; idx += 256) {
        int row = idx & 127, kg = idx >> 7;
        int gr = r0 + row; if (gr >= N) gr = N - 1;
        float4 v = *(const float4*)(h + (size_t)gr * HD + kg * 4);
        uint4 u = make_uint4(f2tf(v.x), f2tf(v.y), f2tf(v.z), f2tf(v.w));
        *(uint4*)(As + row * S2 + kg * 4) = u;
    }

    int lane = tid & 31, wid = tid >> 5;
    int g = lane >> 2, tg = lane & 3;
    int wm = wid & 1, wn = wid >> 1;

    for (int rep = 0; rep < 2; rep++) {
        __syncthreads();
        // stage B[n][k] = W1[(rep*128+k)*128 + n]
        for (int idx = tid; idx < 4096; idx += 256) {
            int n = idx & 127, kg = idx >> 7;
            const float* wp = W1 + (size_t)(rep * 128 + kg * 4) * HD + n;
            uint4 u = make_uint4(f2tf(wp[0]), f2tf(wp[HD]), f2tf(wp[2 * HD]), f2tf(wp[3 * HD]));
            *(uint4*)(Bs + n * S2 + kg * 4) = u;
        }
        __syncthreads();

        float acc[4][4][4];
#pragma unroll
        for (int mt = 0; mt < 4; mt++)
#pragma unroll
            for (int nt = 0; nt < 4; nt++)
#pragma unroll
                for (int q = 0; q < 4; q++) acc[mt][nt][q] = 0.f;

#pragma unroll 1
        for (int kc = 0; kc < 16; kc++) {
            int kb = kc * 8;
            uint32_t a[4][4];
#pragma unroll
            for (int mt = 0; mt < 4; mt++) {
                int rr = wm * 64 + mt * 16 + g;
                a[mt][0] = As[rr * S2 + kb + tg];
                a[mt][1] = As[(rr + 8) * S2 + kb + tg];
                a[mt][2] = As[rr * S2 + kb + tg + 4];
                a[mt][3] = As[(rr + 8) * S2 + kb + tg + 4];
            }
#pragma unroll
            for (int nt = 0; nt < 4; nt++) {
                int cc = wn * 32 + nt * 8 + g;
                uint32_t b[2] = { Bs[cc * S2 + kb + tg], Bs[cc * S2 + kb + tg + 4] };
#pragma unroll
                for (int mt = 0; mt < 4; mt++) mma8(acc[mt][nt], a[mt], b);
            }
        }

        float* out = rep ? g_Pb : g_Pa;
#pragma unroll
        for (int mt = 0; mt < 4; mt++) {
#pragma unroll
            for (int nt = 0; nt < 4; nt++) {
                int col = wn * 32 + nt * 8 + 2 * tg;
                int rr = wm * 64 + mt * 16 + g;
                float bb0 = rep ? 0.f : b1s[col];
                float bb1 = rep ? 0.f : b1s[col + 1];
                if (r0 + rr < N)
                    *(float2*)(out + (size_t)(r0 + rr) * HD + col) =
                        make_float2(acc[mt][nt][0] + bb0, acc[mt][nt][1] + bb1);
                if (r0 + rr + 8 < N)
                    *(float2*)(out + (size_t)(r0 + rr + 8) * HD + col) =
                        make_float2(acc[mt][nt][2] + bb0, acc[mt][nt][3] + bb1);
            }
        }
    }
}

// ---------------------------------------------------------------------------
// Edge: m1 = silu(Pa[row] + Pb[col] + tail(rad,ea));  GEMM2 (tf32 mma);
//       silu(+b2)*mask -> atomic scatter.  256 threads, 128 edges/block.
// ---------------------------------------------------------------------------
#define EO_RS 0
#define EO_CS 512
#define EO_MS 1024
#define EO_B2 1536
#define EO_T  2048
#define EO_A  4864
#define EO_B  (4864 + 67584)
#define EDGE_SMEM (4864 + 2 * 67584)

__global__ void __launch_bounds__(256, 1) edge2_kernel(
    const float* __restrict__ edge_attr, const float* __restrict__ edge_mask,
    const int* __restrict__ ei, const float* __restrict__ W1,
    const float* __restrict__ W2, const float* __restrict__ b2, int E) {
    extern __shared__ char sm[];
    int*      rs  = (int*)(sm + EO_RS);
    int*      cs  = (int*)(sm + EO_CS);
    float*    ms  = (float*)(sm + EO_MS);
    float*    b2s = (float*)(sm + EO_B2);
    float*    Ts  = (float*)(sm + EO_T);       // 5 x 128 tail weights
    uint32_t* As  = (uint32_t*)(sm + EO_A);
    uint32_t* Bs  = (uint32_t*)(sm + EO_B);

    int tid = threadIdx.x;
    int e0 = blockIdx.x * BM;

    if (tid < 128) {
        int ge = e0 + tid;
        int r = 0, c = 0; float mk = 0.f;
        if (ge < E) { r = ei[ge]; c = ei[E + ge]; mk = edge_mask[ge]; }
        rs[tid] = r; cs[tid] = c; ms[tid] = mk;
        b2s[tid] = b2[tid];
    }
    if (tid < 160) {
        int i = tid >> 5, j = (tid & 31) * 4;
        *(float4*)(Ts + i * 128 + j) = *(const float4*)(W1 + (size_t)(256 + i) * HD + j);
    }
    __syncthreads();

    // stage A = tf32(silu(m_pre)); thread: e = tid&127, j-half = tid>>7
    {
        int e = tid & 127, jh = (tid >> 7) * 64;
        int ge = e0 + e;
        int gec = (ge < E) ? ge : 0;
        float rad = g_radial[gec];
        float4 ea = *(const float4*)(edge_attr + (size_t)gec * 4);
        const float* pa = g_Pa + (size_t)rs[e] * HD + jh;
        const float* pb = g_Pb + (size_t)cs[e] * HD + jh;
#pragma unroll 4
        for (int i = 0; i < 16; i++) {
            int j = i * 4;
            float4 va = *(const float4*)(pa + j);
            float4 vb = *(const float4*)(pb + j);
            float4 t0 = *(const float4*)(Ts + 0 * 128 + jh + j);
            float4 t1 = *(const float4*)(Ts + 1 * 128 + jh + j);
            float4 t2 = *(const float4*)(Ts + 2 * 128 + jh + j);
            float4 t3 = *(const float4*)(Ts + 3 * 128 + jh + j);
            float4 t4 = *(const float4*)(Ts + 4 * 128 + jh + j);
            float mx = va.x + vb.x + rad * t0.x + ea.x * t1.x + ea.y * t2.x + ea.z * t3.x + ea.w * t4.x;
            float my = va.y + vb.y + rad * t0.y + ea.x * t1.y + ea.y * t2.y + ea.z * t3.y + ea.w * t4.y;
            float mz = va.z + vb.z + rad * t0.z + ea.x * t1.z + ea.y * t2.z + ea.z * t3.z + ea.w * t4.z;
            float mw = va.w + vb.w + rad * t0.w + ea.x * t1.w + ea.y * t2.w + ea.z * t3.w + ea.w * t4.w;
            uint4 u = make_uint4(f2tf(silu_f(mx)), f2tf(silu_f(my)),
                                 f2tf(silu_f(mz)), f2tf(silu_f(mw)));
            *(uint4*)(As + e * S2 + jh + j) = u;
        }
    }
    // stage B[n][k] = W2[k][n]
    for (int idx = tid; idx < 4096; idx += 256) {
        int n = idx & 127, kg = idx >> 7;
        const float* wp = W2 + (size_t)(kg * 4) * HD + n;
        uint4 u = make_uint4(f2tf(wp[0]), f2tf(wp[HD]), f2tf(wp[2 * HD]), f2tf(wp[3 * HD]));
        *(uint4*)(Bs + n * S2 + kg * 4) = u;
    }
    __syncthreads();

    int lane = tid & 31, wid = tid >> 5;
    int g = lane >> 2, tg = lane & 3;
    int wm = wid & 1, wn = wid >> 1;

    float acc[4][4][4];
#pragma unroll
    for (int mt = 0; mt < 4; mt++)
#pragma unroll
        for (int nt = 0; nt < 4; nt++)
#pragma unroll
            for (int q = 0; q < 4; q++) acc[mt][nt][q] = 0.f;

#pragma unroll 1
    for (int kc = 0; kc < 16; kc++) {
        int kb = kc * 8;
        uint32_t a[4][4];
#pragma unroll
        for (int mt = 0; mt < 4; mt++) {
            int rr = wm * 64 + mt * 16 + g;
            a[mt][0] = As[rr * S2 + kb + tg];
            a[mt][1] = As[(rr + 8) * S2 + kb + tg];
            a[mt][2] = As[rr * S2 + kb + tg + 4];
            a[mt][3] = As[(rr + 8) * S2 + kb + tg + 4];
        }
#pragma unroll
        for (int nt = 0; nt < 4; nt++) {
            int cc = wn * 32 + nt * 8 + g;
            uint32_t b[2] = { Bs[cc * S2 + kb + tg], Bs[cc * S2 + kb + tg + 4] };
#pragma unroll
            for (int mt = 0; mt < 4; mt++) mma8(acc[mt][nt], a[mt], b);
        }
    }

    // epilogue: silu(+b2)*mask -> atomic scatter
#pragma unroll
    for (int mt = 0; mt < 4; mt++) {
#pragma unroll
        for (int nt = 0; nt < 4; nt++) {
            int col = wn * 32 + nt * 8 + 2 * tg;
            int r0 = wm * 64 + mt * 16 + g;
            int r1 = r0 + 8;
            float bb0 = b2s[col], bb1 = b2s[col + 1];
            if (e0 + r0 < E) {
                float mk = ms[r0];
                int base = rs[r0] * HD;
                atomicAdd(&g_agg[base + col],     silu_f(acc[mt][nt][0] + bb0) * mk);
                atomicAdd(&g_agg[base + col + 1], silu_f(acc[mt][nt][1] + bb1) * mk);
            }
            if (e0 + r1 < E) {
                float mk = ms[r1];
                int base = rs[r1] * HD;
                atomicAdd(&g_agg[base + col],     silu_f(acc[mt][nt][2] + bb0) * mk);
                atomicAdd(&g_agg[base + col + 1], silu_f(acc[mt][nt][3] + bb1) * mk);
            }
        }
    }
}

// ---------------------------------------------------------------------------
// Node model (fp32 FFMA, unchanged)
// ---------------------------------------------------------------------------
__global__ void node_kernel(float* __restrict__ h, const float* __restrict__ h0,
                            const float* __restrict__ W1, const float* __restrict__ b1,
                            const float* __restrict__ W2, const float* __restrict__ b2,
                            int N) {
    extern __shared__ float smf[];
    float* As = smf;
    float* Ws = smf + BEN * NKC;

    int tid = threadIdx.x;
    int n0 = blockIdx.x * BEN;

    for (int idx = tid; idx < BEN * NKC; idx += 256) {
        int e = idx / NKC;
        int k = idx - e * NKC;
        int gn = n0 + e;
        float v = 0.f;
        if (gn < N) {
            if (k < HD)           v = h[gn * HD + k];
            else if (k < 2 * HD)  v = g_agg[gn * HD + (k - HD)];
            else                  v = h0[gn * 11 + (k - 2 * HD)];
        }
        As[e * NKC + k] = v;
    }
    __syncthreads();

    int tx = tid & 31;
    int ty = tid >> 5;

    float c1[8][4];
#pragma unroll
    for (int j = 0; j < 4; j++) {
        float bv = b1[tx + 32 * j];
#pragma unroll
        for (int i = 0; i < 8; i++) c1[i][j] = bv;
    }
    for (int k0 = 0; k0 < NKC; k0 += 32) {
        int kc = min(32, NKC - k0);
        __syncthreads();
        for (int idx = tid; idx < kc * HD; idx += 256)
            Ws[idx] = W1[(k0 + (idx >> 7)) * HD + (idx & (HD - 1))];
        __syncthreads();
#pragma unroll 4
        for (int kk = 0; kk < kc; kk++) {
            float w0 = Ws[kk * HD + tx];
            float w1 = Ws[kk * HD + tx + 32];
            float w2 = Ws[kk * HD + tx + 64];
            float w3 = Ws[kk * HD + tx + 96];
#pragma unroll
            for (int i = 0; i < 8; i++) {
                float a = As[(ty + 8 * i) * NKC + k0 + kk];
                c1[i][0] += a * w0; c1[i][1] += a * w1;
                c1[i][2] += a * w2; c1[i][3] += a * w3;
            }
        }
    }
    __syncthreads();

    float* M1 = As;
#pragma unroll
    for (int i = 0; i < 8; i++)
#pragma unroll
        for (int j = 0; j < 4; j++)
            M1[(ty + 8 * i) * HD + tx + 32 * j] = silu_f(c1[i][j]);
    __syncthreads();

    float c2[8][4];
#pragma unroll
    for (int j = 0; j < 4; j++) {
        float bv = b2[tx + 32 * j];
#pragma unroll
        for (int i = 0; i < 8; i++) c2[i][j] = bv;
    }
    for (int k0 = 0; k0 < HD; k0 += 32) {
        __syncthreads();
        for (int idx = tid; idx < 32 * HD; idx += 256)
            Ws[idx] = W2[(k0 + (idx >> 7)) * HD + (idx & (HD - 1))];
        __syncthreads();
#pragma unroll 4
        for (int kk = 0; kk < 32; kk++) {
            float w0 = Ws[kk * HD + tx];
            float w1 = Ws[kk * HD + tx + 32];
            float w2 = Ws[kk * HD + tx + 64];
            float w3 = Ws[kk * HD + tx + 96];
#pragma unroll
            for (int i = 0; i < 8; i++) {
                float a = M1[(ty + 8 * i) * HD + k0 + kk];
                c2[i][0] += a * w0; c2[i][1] += a * w1;
                c2[i][2] += a * w2; c2[i][3] += a * w3;
            }
        }
    }

#pragma unroll
    for (int i = 0; i < 8; i++) {
        int gn = n0 + ty + 8 * i;
        if (gn < N) {
#pragma unroll
            for (int j = 0; j < 4; j++) {
                int o = gn * HD + tx + 32 * j;
                h[o] = h[o] + c2[i][j];
            }
        }
    }
}

// ---------------------------------------------------------------------------
extern "C" void kernel_launch(void* const* d_in, const int* in_sizes, int n_in,
                              void* d_out, int out_size) {
    const float* h0        = (const float*)d_in[0];
    const float* x         = (const float*)d_in[1];
    const int*   ei        = (const int*)  d_in[2];
    const float* edge_attr = (const float*)d_in[3];
    const float* edge_mask = (const float*)d_in[5];

    int wi = (in_sizes[6] == 1) ? 7 : 6;
    const float* emb_w = (const float*)d_in[wi + 0];
    const float* emb_b = (const float*)d_in[wi + 1];
    const float* ew1   = (const float*)d_in[wi + 2];
    const float* eb1   = (const float*)d_in[wi + 3];
    const float* ew2   = (const float*)d_in[wi + 4];
    const float* eb2   = (const float*)d_in[wi + 5];
    const float* nw1   = (const float*)d_in[wi + 6];
    const float* nb1   = (const float*)d_in[wi + 7];
    const float* nw2   = (const float*)d_in[wi + 8];
    const float* nb2   = (const float*)d_in[wi + 9];

    float* h = (float*)d_out;
    int N = in_sizes[0] / 11;
    int E = in_sizes[3] / 4;

    const int NODE_SMEM = (BEN * NKC + 32 * HD) * 4;
    cudaFuncSetAttribute(proj_kernel,  cudaFuncAttributeMaxDynamicSharedMemorySize, PROJ_SMEM);
    cudaFuncSetAttribute(edge2_kernel, cudaFuncAttributeMaxDynamicSharedMemorySize, EDGE_SMEM);
    cudaFuncSetAttribute(node_kernel,  cudaFuncAttributeMaxDynamicSharedMemorySize, NODE_SMEM);

    radial_kernel<<<(E + 255) / 256, 256>>>(x, ei, E);
    embed_kernel<<<N, HD>>>(h0, emb_w, emb_b, h);

    int n4 = (N * HD) / 4;
    int pblocks = (N + 127) / 128;
    int eblocks = (E + BM - 1) / BM;
    int nblocks = (N + BEN - 1) / BEN;

    for (int l = 0; l < NL; l++) {
        proj_kernel<<<pblocks, 256, PROJ_SMEM>>>(h, ew1 + (size_t)l * 261 * HD,
                                                 eb1 + l * HD, N);
        zero_agg_kernel<<<(n4 + 255) / 256, 256>>>(n4);
        edge2_kernel<<<eblocks, 256, EDGE_SMEM>>>(edge_attr, edge_mask, ei,
                                                  ew1 + (size_t)l * 261 * HD,
                                                  ew2 + (size_t)l * HD * HD, eb2 + l * HD, E);
        node_kernel<<<nblocks, 256, NODE_SMEM>>>(h, h0,
                                                 nw1 + (size_t)l * NKC * HD, nb1 + l * HD,
                                                 nw2 + (size_t)l * HD * HD, nb2 + l * HD, N);
    }
}

// round 10
// speedup vs baseline: 3.9061x; 1.2241x over previous
#include <cuda_runtime.h>
#include <cstdint>

#define HD  128
#define NL  4
#define BM  128
#define S2  132   // smem k-stride (words): conflict-free frag reads

__device__ float g_radial[800000];
__device__ float g_agg[50000 * HD];
__device__ float g_Pa[50000 * HD];
__device__ float g_Pb[50000 * HD];

__device__ __forceinline__ float silu_f(float v) {
    return __fdividef(v, 1.0f + __expf(-v));
}
__device__ __forceinline__ uint32_t f2tf(float f) {
    uint32_t r;
    asm("cvt.rna.tf32.f32 %0, %1;" : "=r"(r) : "f"(f));
    return r;
}
__device__ __forceinline__ void mma8(float* d, const uint32_t* a, const uint32_t* b) {
    asm volatile(
        "mma.sync.aligned.m16n8k8.row.col.f32.tf32.tf32.f32 "
        "{%0,%1,%2,%3}, {%4,%5,%6,%7}, {%8,%9}, {%0,%1,%2,%3};"
        : "+f"(d[0]), "+f"(d[1]), "+f"(d[2]), "+f"(d[3])
        : "r"(a[0]), "r"(a[1]), "r"(a[2]), "r"(a[3]), "r"(b[0]), "r"(b[1]));
}
__device__ __forceinline__ void red_v2(float* p, float a, float b) {
    asm volatile("red.global.add.v2.f32 [%0], {%1, %2};"
                 :: "l"(p), "f"(a), "f"(b) : "memory");
}

// ---------------------------------------------------------------------------
__global__ void radial_kernel(const float* __restrict__ x, const int* __restrict__ ei, int E) {
    int e = blockIdx.x * blockDim.x + threadIdx.x;
    if (e >= E) return;
    int r = ei[e], c = ei[E + e];
    float dx = x[r * 3 + 0] - x[c * 3 + 0];
    float dy = x[r * 3 + 1] - x[c * 3 + 1];
    float dz = x[r * 3 + 2] - x[c * 3 + 2];
    g_radial[e] = dx * dx + dy * dy + dz * dz;
}

__global__ void embed_kernel(const float* __restrict__ h0, const float* __restrict__ w,
                             const float* __restrict__ b, float* __restrict__ h) {
    __shared__ float s[11];
    int n = blockIdx.x;
    int f = threadIdx.x;
    if (f < 11) s[f] = h0[n * 11 + f];
    __syncthreads();
    float acc = b[f];
#pragma unroll
    for (int k = 0; k < 11; k++) acc += s[k] * w[k * HD + f];
    h[n * HD + f] = acc;
}

__global__ void zero_agg_kernel(int n4) {
    int i = blockIdx.x * blockDim.x + threadIdx.x;
    if (i < n4) reinterpret_cast<float4*>(g_agg)[i] = make_float4(0.f, 0.f, 0.f, 0.f);
}

// ---------------------------------------------------------------------------
// proj: Pa = h @ W1[0:128] + b1 ; Pb = h @ W1[128:256]
// ---------------------------------------------------------------------------
#define PROJ_SMEM (512 + 2 * 67584)
__global__ void __launch_bounds__(256, 1) proj_kernel(
    const float* __restrict__ h, const float* __restrict__ W1,
    const float* __restrict__ b1, int N) {
    extern __shared__ char sm[];
    float*    b1s = (float*)sm;
    uint32_t* As  = (uint32_t*)(sm + 512);
    uint32_t* Bs  = (uint32_t*)(sm + 512 + 67584);

    int tid = threadIdx.x;
    int r0 = blockIdx.x * 128;
    if (tid < 128) b1s[tid] = b1[tid];

    for (int idx = tid; idx < 4096; idx += 256) {
        int row = idx & 127, kg = idx >> 7;
        int gr = r0 + row; if (gr >= N) gr = N - 1;
        float4 v = *(const float4*)(h + (size_t)gr * HD + kg * 4);
        uint4 u = make_uint4(f2tf(v.x), f2tf(v.y), f2tf(v.z), f2tf(v.w));
        *(uint4*)(As + row * S2 + kg * 4) = u;
    }

    int lane = tid & 31, wid = tid >> 5;
    int g = lane >> 2, tg = lane & 3;
    int wm = wid & 1, wn = wid >> 1;

    for (int rep = 0; rep < 2; rep++) {
        __syncthreads();
        for (int idx = tid; idx < 4096; idx += 256) {
            int n = idx & 127, kg = idx >> 7;
            const float* wp = W1 + (size_t)(rep * 128 + kg * 4) * HD + n;
            uint4 u = make_uint4(f2tf(wp[0]), f2tf(wp[HD]), f2tf(wp[2 * HD]), f2tf(wp[3 * HD]));
            *(uint4*)(Bs + n * S2 + kg * 4) = u;
        }
        __syncthreads();

        float acc[4][4][4];
#pragma unroll
        for (int mt = 0; mt < 4; mt++)
#pragma unroll
            for (int nt = 0; nt < 4; nt++)
#pragma unroll
                for (int q = 0; q < 4; q++) acc[mt][nt][q] = 0.f;

#pragma unroll 1
        for (int kc = 0; kc < 16; kc++) {
            int kb = kc * 8;
            uint32_t a[4][4];
#pragma unroll
            for (int mt = 0; mt < 4; mt++) {
                int rr = wm * 64 + mt * 16 + g;
                a[mt][0] = As[rr * S2 + kb + tg];
                a[mt][1] = As[(rr + 8) * S2 + kb + tg];
                a[mt][2] = As[rr * S2 + kb + tg + 4];
                a[mt][3] = As[(rr + 8) * S2 + kb + tg + 4];
            }
#pragma unroll
            for (int nt = 0; nt < 4; nt++) {
                int cc = wn * 32 + nt * 8 + g;
                uint32_t b[2] = { Bs[cc * S2 + kb + tg], Bs[cc * S2 + kb + tg + 4] };
#pragma unroll
                for (int mt = 0; mt < 4; mt++) mma8(acc[mt][nt], a[mt], b);
            }
        }

        float* out = rep ? g_Pb : g_Pa;
#pragma unroll
        for (int mt = 0; mt < 4; mt++) {
#pragma unroll
            for (int nt = 0; nt < 4; nt++) {
                int col = wn * 32 + nt * 8 + 2 * tg;
                int rr = wm * 64 + mt * 16 + g;
                float bb0 = rep ? 0.f : b1s[col];
                float bb1 = rep ? 0.f : b1s[col + 1];
                if (r0 + rr < N)
                    *(float2*)(out + (size_t)(r0 + rr) * HD + col) =
                        make_float2(acc[mt][nt][0] + bb0, acc[mt][nt][1] + bb1);
                if (r0 + rr + 8 < N)
                    *(float2*)(out + (size_t)(r0 + rr + 8) * HD + col) =
                        make_float2(acc[mt][nt][2] + bb0, acc[mt][nt][3] + bb1);
            }
        }
    }
}

// ---------------------------------------------------------------------------
// Edge: m1 = silu(Pa[row]+Pb[col]+tail); GEMM2; silu(+b2)*mask -> red.v2 scatter
// ---------------------------------------------------------------------------
#define EO_RS 0
#define EO_CS 512
#define EO_MS 1024
#define EO_B2 1536
#define EO_T  2048
#define EO_A  4864
#define EO_B  (4864 + 67584)
#define EDGE_SMEM (4864 + 2 * 67584)

__global__ void __launch_bounds__(256, 1) edge2_kernel(
    const float* __restrict__ edge_attr, const float* __restrict__ edge_mask,
    const int* __restrict__ ei, const float* __restrict__ W1,
    const float* __restrict__ W2, const float* __restrict__ b2, int E) {
    extern __shared__ char sm[];
    int*      rs  = (int*)(sm + EO_RS);
    int*      cs  = (int*)(sm + EO_CS);
    float*    ms  = (float*)(sm + EO_MS);
    float*    b2s = (float*)(sm + EO_B2);
    float*    Ts  = (float*)(sm + EO_T);
    uint32_t* As  = (uint32_t*)(sm + EO_A);
    uint32_t* Bs  = (uint32_t*)(sm + EO_B);

    int tid = threadIdx.x;
    int e0 = blockIdx.x * BM;

    if (tid < 128) {
        int ge = e0 + tid;
        int r = 0, c = 0; float mk = 0.f;
        if (ge < E) { r = ei[ge]; c = ei[E + ge]; mk = edge_mask[ge]; }
        rs[tid] = r; cs[tid] = c; ms[tid] = mk;
        b2s[tid] = b2[tid];
    }
    if (tid < 160) {
        int i = tid >> 5, j = (tid & 31) * 4;
        *(float4*)(Ts + i * 128 + j) = *(const float4*)(W1 + (size_t)(256 + i) * HD + j);
    }
    __syncthreads();

    {
        int e = tid & 127, jh = (tid >> 7) * 64;
        int ge = e0 + e;
        int gec = (ge < E) ? ge : 0;
        float rad = g_radial[gec];
        float4 ea = *(const float4*)(edge_attr + (size_t)gec * 4);
        const float* pa = g_Pa + (size_t)rs[e] * HD + jh;
        const float* pb = g_Pb + (size_t)cs[e] * HD + jh;
#pragma unroll 4
        for (int i = 0; i < 16; i++) {
            int j = i * 4;
            float4 va = *(const float4*)(pa + j);
            float4 vb = *(const float4*)(pb + j);
            float4 t0 = *(const float4*)(Ts + 0 * 128 + jh + j);
            float4 t1 = *(const float4*)(Ts + 1 * 128 + jh + j);
            float4 t2 = *(const float4*)(Ts + 2 * 128 + jh + j);
            float4 t3 = *(const float4*)(Ts + 3 * 128 + jh + j);
            float4 t4 = *(const float4*)(Ts + 4 * 128 + jh + j);
            float mx = va.x + vb.x + rad * t0.x + ea.x * t1.x + ea.y * t2.x + ea.z * t3.x + ea.w * t4.x;
            float my = va.y + vb.y + rad * t0.y + ea.x * t1.y + ea.y * t2.y + ea.z * t3.y + ea.w * t4.y;
            float mz = va.z + vb.z + rad * t0.z + ea.x * t1.z + ea.y * t2.z + ea.z * t3.z + ea.w * t4.z;
            float mw = va.w + vb.w + rad * t0.w + ea.x * t1.w + ea.y * t2.w + ea.z * t3.w + ea.w * t4.w;
            uint4 u = make_uint4(f2tf(silu_f(mx)), f2tf(silu_f(my)),
                                 f2tf(silu_f(mz)), f2tf(silu_f(mw)));
            *(uint4*)(As + e * S2 + jh + j) = u;
        }
    }
    for (int idx = tid; idx < 4096; idx += 256) {
        int n = idx & 127, kg = idx >> 7;
        const float* wp = W2 + (size_t)(kg * 4) * HD + n;
        uint4 u = make_uint4(f2tf(wp[0]), f2tf(wp[HD]), f2tf(wp[2 * HD]), f2tf(wp[3 * HD]));
        *(uint4*)(Bs + n * S2 + kg * 4) = u;
    }
    __syncthreads();

    int lane = tid & 31, wid = tid >> 5;
    int g = lane >> 2, tg = lane & 3;
    int wm = wid & 1, wn = wid >> 1;

    float acc[4][4][4];
#pragma unroll
    for (int mt = 0; mt < 4; mt++)
#pragma unroll
        for (int nt = 0; nt < 4; nt++)
#pragma unroll
            for (int q = 0; q < 4; q++) acc[mt][nt][q] = 0.f;

#pragma unroll 1
    for (int kc = 0; kc < 16; kc++) {
        int kb = kc * 8;
        uint32_t a[4][4];
#pragma unroll
        for (int mt = 0; mt < 4; mt++) {
            int rr = wm * 64 + mt * 16 + g;
            a[mt][0] = As[rr * S2 + kb + tg];
            a[mt][1] = As[(rr + 8) * S2 + kb + tg];
            a[mt][2] = As[rr * S2 + kb + tg + 4];
            a[mt][3] = As[(rr + 8) * S2 + kb + tg + 4];
        }
#pragma unroll
        for (int nt = 0; nt < 4; nt++) {
            int cc = wn * 32 + nt * 8 + g;
            uint32_t b[2] = { Bs[cc * S2 + kb + tg], Bs[cc * S2 + kb + tg + 4] };
#pragma unroll
            for (int mt = 0; mt < 4; mt++) mma8(acc[mt][nt], a[mt], b);
        }
    }

#pragma unroll
    for (int mt = 0; mt < 4; mt++) {
#pragma unroll
        for (int nt = 0; nt < 4; nt++) {
            int col = wn * 32 + nt * 8 + 2 * tg;
            int r0 = wm * 64 + mt * 16 + g;
            int r1 = r0 + 8;
            float bb0 = b2s[col], bb1 = b2s[col + 1];
            if (e0 + r0 < E) {
                float mk = ms[r0];
                red_v2(&g_agg[rs[r0] * HD + col],
                       silu_f(acc[mt][nt][0] + bb0) * mk,
                       silu_f(acc[mt][nt][1] + bb1) * mk);
            }
            if (e0 + r1 < E) {
                float mk = ms[r1];
                red_v2(&g_agg[rs[r1] * HD + col],
                       silu_f(acc[mt][nt][2] + bb0) * mk,
                       silu_f(acc[mt][nt][3] + bb1) * mk);
            }
        }
    }
}

// ---------------------------------------------------------------------------
// Node model on tensor cores:
//   out1 = silu(h@nw1[0:128] + agg@nw1[128:256] + h0@nw1[256:267] + b1)
//   h   += out1@nw2 + b2
// 256 threads, 128 nodes/block.
// ---------------------------------------------------------------------------
#define NO_B1 0
#define NO_B2 512
#define NO_H0 1024                 // 128 x 12 floats = 6144
#define NO_TN 7168                 // 11 x 128 floats = 5632
#define NO_A  12800
#define NO_B  (12800 + 67584)
#define NODE_SMEM (12800 + 2 * 67584)

__global__ void __launch_bounds__(256, 1) node_mma_kernel(
    float* __restrict__ h, const float* __restrict__ h0,
    const float* __restrict__ W1, const float* __restrict__ b1,
    const float* __restrict__ W2, const float* __restrict__ b2, int N) {
    extern __shared__ char sm[];
    float*    b1s = (float*)(sm + NO_B1);
    float*    b2s = (float*)(sm + NO_B2);
    float*    h0s = (float*)(sm + NO_H0);   // [128][12]
    float*    Tn  = (float*)(sm + NO_TN);   // [11][128]
    uint32_t* As  = (uint32_t*)(sm + NO_A);
    uint32_t* Bs  = (uint32_t*)(sm + NO_B);

    int tid = threadIdx.x;
    int r0 = blockIdx.x * 128;
    if (tid < 128) { b1s[tid] = b1[tid]; b2s[tid] = b2[tid]; }
    // h0 tile [128][11] -> smem stride 12
    {
        int row = tid & 127, half = tid >> 7;   // 6 elems each half (0..5 / 6..10)
        int gr = r0 + row; if (gr >= N) gr = N - 1;
        const float* src = h0 + (size_t)gr * 11;
#pragma unroll
        for (int q = 0; q < 6; q++) {
            int k = half * 6 + q;
            if (k < 11) h0s[row * 12 + k] = src[k];
        }
    }
    // W1 tail rows 256..266 -> Tn[11][128]
    for (int idx = tid; idx < 11 * 32; idx += 256) {
        int i = idx >> 5, j = (idx & 31) * 4;
        *(float4*)(Tn + i * 128 + j) = *(const float4*)(W1 + (size_t)(256 + i) * HD + j);
    }

    int lane = tid & 31, wid = tid >> 5;
    int g = lane >> 2, tg = lane & 3;
    int wm = wid & 1, wn = wid >> 1;

    float acc[4][4][4];
#pragma unroll
    for (int mt = 0; mt < 4; mt++)
#pragma unroll
        for (int nt = 0; nt < 4; nt++)
#pragma unroll
            for (int q = 0; q < 4; q++) acc[mt][nt][q] = 0.f;

    // ---- GEMM1: rep 0 uses h, rep 1 uses agg ----
    for (int rep = 0; rep < 2; rep++) {
        __syncthreads();
        const float* src = rep ? g_agg : h;
        for (int idx = tid; idx < 4096; idx += 256) {
            int row = idx & 127, kg = idx >> 7;
            int gr = r0 + row; if (gr >= N) gr = N - 1;
            float4 v = *(const float4*)(src + (size_t)gr * HD + kg * 4);
            uint4 u = make_uint4(f2tf(v.x), f2tf(v.y), f2tf(v.z), f2tf(v.w));
            *(uint4*)(As + row * S2 + kg * 4) = u;
        }
        for (int idx = tid; idx < 4096; idx += 256) {
            int n = idx & 127, kg = idx >> 7;
            const float* wp = W1 + (size_t)(rep * 128 + kg * 4) * HD + n;
            uint4 u = make_uint4(f2tf(wp[0]), f2tf(wp[HD]), f2tf(wp[2 * HD]), f2tf(wp[3 * HD]));
            *(uint4*)(Bs + n * S2 + kg * 4) = u;
        }
        __syncthreads();

#pragma unroll 1
        for (int kc = 0; kc < 16; kc++) {
            int kb = kc * 8;
            uint32_t a[4][4];
#pragma unroll
            for (int mt = 0; mt < 4; mt++) {
                int rr = wm * 64 + mt * 16 + g;
                a[mt][0] = As[rr * S2 + kb + tg];
                a[mt][1] = As[(rr + 8) * S2 + kb + tg];
                a[mt][2] = As[rr * S2 + kb + tg + 4];
                a[mt][3] = As[(rr + 8) * S2 + kb + tg + 4];
            }
#pragma unroll
            for (int nt = 0; nt < 4; nt++) {
                int cc = wn * 32 + nt * 8 + g;
                uint32_t b[2] = { Bs[cc * S2 + kb + tg], Bs[cc * S2 + kb + tg + 4] };
#pragma unroll
                for (int mt = 0; mt < 4; mt++) mma8(acc[mt][nt], a[mt], b);
            }
        }
    }
    __syncthreads();

    // ---- epilogue 1: + b1 + h0-tail, silu, tf32 -> As ----
#pragma unroll
    for (int mt = 0; mt < 4; mt++) {
        int rr = wm * 64 + mt * 16 + g;
#pragma unroll
        for (int nt = 0; nt < 4; nt++) {
            int col = wn * 32 + nt * 8 + 2 * tg;
            float v[4];
            v[0] = acc[mt][nt][0] + b1s[col];
            v[1] = acc[mt][nt][1] + b1s[col + 1];
            v[2] = acc[mt][nt][2] + b1s[col];
            v[3] = acc[mt][nt][3] + b1s[col + 1];
#pragma unroll
            for (int k = 0; k < 11; k++) {
                float t0 = Tn[k * 128 + col];
                float t1 = Tn[k * 128 + col + 1];
                float a0 = h0s[rr * 12 + k];
                float a1 = h0s[(rr + 8) * 12 + k];
                v[0] += a0 * t0; v[1] += a0 * t1;
                v[2] += a1 * t0; v[3] += a1 * t1;
            }
            As[rr * S2 + col]           = f2tf(silu_f(v[0]));
            As[rr * S2 + col + 1]       = f2tf(silu_f(v[1]));
            As[(rr + 8) * S2 + col]     = f2tf(silu_f(v[2]));
            As[(rr + 8) * S2 + col + 1] = f2tf(silu_f(v[3]));
        }
    }
    // stage B = nw2^T
    for (int idx = tid; idx < 4096; idx += 256) {
        int n = idx & 127, kg = idx >> 7;
        const float* wp = W2 + (size_t)(kg * 4) * HD + n;
        uint4 u = make_uint4(f2tf(wp[0]), f2tf(wp[HD]), f2tf(wp[2 * HD]), f2tf(wp[3 * HD]));
        *(uint4*)(Bs + n * S2 + kg * 4) = u;
    }
#pragma unroll
    for (int mt = 0; mt < 4; mt++)
#pragma unroll
        for (int nt = 0; nt < 4; nt++)
#pragma unroll
            for (int q = 0; q < 4; q++) acc[mt][nt][q] = 0.f;
    __syncthreads();

    // ---- GEMM2 ----
#pragma unroll 1
    for (int kc = 0; kc < 16; kc++) {
        int kb = kc * 8;
        uint32_t a[4][4];
#pragma unroll
        for (int mt = 0; mt < 4; mt++) {
            int rr = wm * 64 + mt * 16 + g;
            a[mt][0] = As[rr * S2 + kb + tg];
            a[mt][1] = As[(rr + 8) * S2 + kb + tg];
            a[mt][2] = As[rr * S2 + kb + tg + 4];
            a[mt][3] = As[(rr + 8) * S2 + kb + tg + 4];
        }
#pragma unroll
        for (int nt = 0; nt < 4; nt++) {
            int cc = wn * 32 + nt * 8 + g;
            uint32_t b[2] = { Bs[cc * S2 + kb + tg], Bs[cc * S2 + kb + tg + 4] };
#pragma unroll
            for (int mt = 0; mt < 4; mt++) mma8(acc[mt][nt], a[mt], b);
        }
    }

    // ---- epilogue 2: h += out + b2 ----
#pragma unroll
    for (int mt = 0; mt < 4; mt++) {
        int rr = wm * 64 + mt * 16 + g;
#pragma unroll
        for (int nt = 0; nt < 4; nt++) {
            int col = wn * 32 + nt * 8 + 2 * tg;
            float bb0 = b2s[col], bb1 = b2s[col + 1];
            if (r0 + rr < N) {
                float* p = h + (size_t)(r0 + rr) * HD + col;
                float2 old = *(float2*)p;
                *(float2*)p = make_float2(old.x + acc[mt][nt][0] + bb0,
                                          old.y + acc[mt][nt][1] + bb1);
            }
            if (r0 + rr + 8 < N) {
                float* p = h + (size_t)(r0 + rr + 8) * HD + col;
                float2 old = *(float2*)p;
                *(float2*)p = make_float2(old.x + acc[mt][nt][2] + bb0,
                                          old.y + acc[mt][nt][3] + bb1);
            }
        }
    }
}

// ---------------------------------------------------------------------------
extern "C" void kernel_launch(void* const* d_in, const int* in_sizes, int n_in,
                              void* d_out, int out_size) {
    const float* h0        = (const float*)d_in[0];
    const float* x         = (const float*)d_in[1];
    const int*   ei        = (const int*)  d_in[2];
    const float* edge_attr = (const float*)d_in[3];
    const float* edge_mask = (const float*)d_in[5];

    int wi = (in_sizes[6] == 1) ? 7 : 6;
    const float* emb_w = (const float*)d_in[wi + 0];
    const float* emb_b = (const float*)d_in[wi + 1];
    const float* ew1   = (const float*)d_in[wi + 2];
    const float* eb1   = (const float*)d_in[wi + 3];
    const float* ew2   = (const float*)d_in[wi + 4];
    const float* eb2   = (const float*)d_in[wi + 5];
    const float* nw1   = (const float*)d_in[wi + 6];
    const float* nb1   = (const float*)d_in[wi + 7];
    const float* nw2   = (const float*)d_in[wi + 8];
    const float* nb2   = (const float*)d_in[wi + 9];

    float* h = (float*)d_out;
    int N = in_sizes[0] / 11;
    int E = in_sizes[3] / 4;

    cudaFuncSetAttribute(proj_kernel,     cudaFuncAttributeMaxDynamicSharedMemorySize, PROJ_SMEM);
    cudaFuncSetAttribute(edge2_kernel,    cudaFuncAttributeMaxDynamicSharedMemorySize, EDGE_SMEM);
    cudaFuncSetAttribute(node_mma_kernel, cudaFuncAttributeMaxDynamicSharedMemorySize, NODE_SMEM);

    radial_kernel<<<(E + 255) / 256, 256>>>(x, ei, E);
    embed_kernel<<<N, HD>>>(h0, emb_w, emb_b, h);

    int n4 = (N * HD) / 4;
    int pblocks = (N + 127) / 128;
    int eblocks = (E + BM - 1) / BM;

    for (int l = 0; l < NL; l++) {
        proj_kernel<<<pblocks, 256, PROJ_SMEM>>>(h, ew1 + (size_t)l * 261 * HD,
                                                 eb1 + l * HD, N);
        zero_agg_kernel<<<(n4 + 255) / 256, 256>>>(n4);
        edge2_kernel<<<eblocks, 256, EDGE_SMEM>>>(edge_attr, edge_mask, ei,
                                                  ew1 + (size_t)l * 261 * HD,
                                                  ew2 + (size_t)l * HD * HD, eb2 + l * HD, E);
        node_mma_kernel<<<pblocks, 256, NODE_SMEM>>>(h, h0,
                                                     nw1 + (size_t)l * 267 * HD, nb1 + l * HD,
                                                     nw2 + (size_t)l * HD * HD, nb2 + l * HD, N);
    }
}

// round 12
// speedup vs baseline: 4.4716x; 1.1448x over previous
#include <cuda_runtime.h>
#include <cstdint>

#define HD  128
#define NL  4
#define BM  128
#define S2  132   // smem k-stride (words): conflict-free frag reads

__device__ float g_radial[800000];
__device__ float g_agg[50000 * HD];
__device__ float g_Pa[50000 * HD];
__device__ float g_Pb[50000 * HD];
// pre-transposed tf32 weights: [layer][chunk][n*128+k], chunks:
// 0: ew1 rows 0-127   1: ew1 rows 128-255   2: ew2
// 3: nw1 rows 0-127   4: nw1 rows 128-255   5: nw2
__device__ uint32_t g_WT[NL * 6 * 128 * 128];

__device__ __forceinline__ float silu_f(float v) {
    return __fdividef(v, 1.0f + __expf(-v));
}
__device__ __forceinline__ uint32_t f2tf(float f) {
    uint32_t r;
    asm("cvt.rna.tf32.f32 %0, %1;" : "=r"(r) : "f"(f));
    return r;
}
__device__ __forceinline__ void mma8(float* d, const uint32_t* a, const uint32_t* b) {
    asm volatile(
        "mma.sync.aligned.m16n8k8.row.col.f32.tf32.tf32.f32 "
        "{%0,%1,%2,%3}, {%4,%5,%6,%7}, {%8,%9}, {%0,%1,%2,%3};"
        : "+f"(d[0]), "+f"(d[1]), "+f"(d[2]), "+f"(d[3])
        : "r"(a[0]), "r"(a[1]), "r"(a[2]), "r"(a[3]), "r"(b[0]), "r"(b[1]));
}
__device__ __forceinline__ void red_v2(float* p, float a, float b) {
    asm volatile("red.global.add.v2.f32 [%0], {%1, %2};"
                 :: "l"(p), "f"(a), "f"(b) : "memory");
}

// ---------------------------------------------------------------------------
// Weight transpose + tf32 convert: g_WT[chunk][n*128+k] = tf32(W[k][n])
// grid (64, 24), 256 threads. Coalesced reads (consecutive n).
// ---------------------------------------------------------------------------
__global__ void wtrans_kernel(const float* __restrict__ ew1, const float* __restrict__ ew2,
                              const float* __restrict__ nw1, const float* __restrict__ nw2) {
    int idx = blockIdx.x * 256 + threadIdx.x;      // 0..16383 within chunk
    int n = idx >> 7, k = idx & 127;
    int chunk = blockIdx.y;
    int l = chunk / 6, s = chunk - l * 6;
    const float* src;
    switch (s) {
        case 0: src = ew1 + (size_t)l * 261 * HD;            break;
        case 1: src = ew1 + (size_t)l * 261 * HD + 128 * HD; break;
        case 2: src = ew2 + (size_t)l * HD * HD;             break;
        case 3: src = nw1 + (size_t)l * 267 * HD;            break;
        case 4: src = nw1 + (size_t)l * 267 * HD + 128 * HD; break;
        default: src = nw2 + (size_t)l * HD * HD;            break;
    }
    g_WT[(size_t)chunk * 16384 + (size_t)n * 128 + k] = f2tf(src[(size_t)k * HD + n]);
}

// copy one pre-transposed chunk into smem (stride S2), coalesced uint4
__device__ __forceinline__ void stage_wt(uint32_t* Bs, int chunk, int tid) {
    const uint4* src = (const uint4*)(g_WT + (size_t)chunk * 16384);
#pragma unroll 4
    for (int idx = tid; idx < 4096; idx += 256) {
        int n = idx >> 5, g4 = idx & 31;
        *(uint4*)(Bs + n * S2 + g4 * 4) = src[idx];
    }
}

// ---------------------------------------------------------------------------
__global__ void radial_kernel(const float* __restrict__ x, const int* __restrict__ ei, int E) {
    int e = blockIdx.x * blockDim.x + threadIdx.x;
    if (e >= E) return;
    int r = ei[e], c = ei[E + e];
    float dx = x[r * 3 + 0] - x[c * 3 + 0];
    float dy = x[r * 3 + 1] - x[c * 3 + 1];
    float dz = x[r * 3 + 2] - x[c * 3 + 2];
    g_radial[e] = dx * dx + dy * dy + dz * dz;
}

__global__ void embed_kernel(const float* __restrict__ h0, const float* __restrict__ w,
                             const float* __restrict__ b, float* __restrict__ h) {
    __shared__ float s[11];
    int n = blockIdx.x;
    int f = threadIdx.x;
    if (f < 11) s[f] = h0[n * 11 + f];
    __syncthreads();
    float acc = b[f];
#pragma unroll
    for (int k = 0; k < 11; k++) acc += s[k] * w[k * HD + f];
    h[n * HD + f] = acc;
}

__global__ void zero_agg_kernel(int n4) {
    int i = blockIdx.x * blockDim.x + threadIdx.x;
    if (i < n4) reinterpret_cast<float4*>(g_agg)[i] = make_float4(0.f, 0.f, 0.f, 0.f);
}

// ---------------------------------------------------------------------------
// proj: Pa = h @ W1[0:128] + b1 ; Pb = h @ W1[128:256]
// ---------------------------------------------------------------------------
#define PROJ_SMEM (512 + 2 * 67584)
__global__ void __launch_bounds__(256, 1) proj_kernel(
    const float* __restrict__ h, const float* __restrict__ b1,
    int wchunk, int N) {
    extern __shared__ char sm[];
    float*    b1s = (float*)sm;
    uint32_t* As  = (uint32_t*)(sm + 512);
    uint32_t* Bs  = (uint32_t*)(sm + 512 + 67584);

    int tid = threadIdx.x;
    int r0 = blockIdx.x * 128;
    if (tid < 128) b1s[tid] = b1[tid];

    for (int idx = tid; idx < 4096; idx += 256) {
        int row = idx & 127, kg = idx >> 7;
        int gr = r0 + row; if (gr >= N) gr = N - 1;
        float4 v = *(const float4*)(h + (size_t)gr * HD + kg * 4);
        uint4 u = make_uint4(f2tf(v.x), f2tf(v.y), f2tf(v.z), f2tf(v.w));
        *(uint4*)(As + row * S2 + kg * 4) = u;
    }

    int lane = tid & 31, wid = tid >> 5;
    int g = lane >> 2, tg = lane & 3;
    int wm = wid & 1, wn = wid >> 1;

    for (int rep = 0; rep < 2; rep++) {
        __syncthreads();
        stage_wt(Bs, wchunk + rep, tid);
        __syncthreads();

        float acc[4][4][4];
#pragma unroll
        for (int mt = 0; mt < 4; mt++)
#pragma unroll
            for (int nt = 0; nt < 4; nt++)
#pragma unroll
                for (int q = 0; q < 4; q++) acc[mt][nt][q] = 0.f;

#pragma unroll 1
        for (int kc = 0; kc < 16; kc++) {
            int kb = kc * 8;
            uint32_t a[4][4];
#pragma unroll
            for (int mt = 0; mt < 4; mt++) {
                int rr = wm * 64 + mt * 16 + g;
                a[mt][0] = As[rr * S2 + kb + tg];
                a[mt][1] = As[(rr + 8) * S2 + kb + tg];
                a[mt][2] = As[rr * S2 + kb + tg + 4];
                a[mt][3] = As[(rr + 8) * S2 + kb + tg + 4];
            }
#pragma unroll
            for (int nt = 0; nt < 4; nt++) {
                int cc = wn * 32 + nt * 8 + g;
                uint32_t b[2] = { Bs[cc * S2 + kb + tg], Bs[cc * S2 + kb + tg + 4] };
#pragma unroll
                for (int mt = 0; mt < 4; mt++) mma8(acc[mt][nt], a[mt], b);
            }
        }

        float* out = rep ? g_Pb : g_Pa;
#pragma unroll
        for (int mt = 0; mt < 4; mt++) {
#pragma unroll
            for (int nt = 0; nt < 4; nt++) {
                int col = wn * 32 + nt * 8 + 2 * tg;
                int rr = wm * 64 + mt * 16 + g;
                float bb0 = rep ? 0.f : b1s[col];
                float bb1 = rep ? 0.f : b1s[col + 1];
                if (r0 + rr < N)
                    *(float2*)(out + (size_t)(r0 + rr) * HD + col) =
                        make_float2(acc[mt][nt][0] + bb0, acc[mt][nt][1] + bb1);
                if (r0 + rr + 8 < N)
                    *(float2*)(out + (size_t)(r0 + rr + 8) * HD + col) =
                        make_float2(acc[mt][nt][2] + bb0, acc[mt][nt][3] + bb1);
            }
        }
    }
}

// ---------------------------------------------------------------------------
// Edge: m1 = silu(Pa[row]+Pb[col]+tail); GEMM2; silu(+b2)*mask -> red.v2 scatter
// ---------------------------------------------------------------------------
#define EO_RS 0
#define EO_CS 512
#define EO_MS 1024
#define EO_B2 1536
#define EO_T  2048
#define EO_A  4864
#define EO_B  (4864 + 67584)
#define EDGE_SMEM (4864 + 2 * 67584)

__global__ void __launch_bounds__(256, 1) edge2_kernel(
    const float* __restrict__ edge_attr, const float* __restrict__ edge_mask,
    const int* __restrict__ ei, const float* __restrict__ W1,
    const float* __restrict__ b2, int wchunk, int E) {
    extern __shared__ char sm[];
    int*      rs  = (int*)(sm + EO_RS);
    int*      cs  = (int*)(sm + EO_CS);
    float*    ms  = (float*)(sm + EO_MS);
    float*    b2s = (float*)(sm + EO_B2);
    float*    Ts  = (float*)(sm + EO_T);
    uint32_t* As  = (uint32_t*)(sm + EO_A);
    uint32_t* Bs  = (uint32_t*)(sm + EO_B);

    int tid = threadIdx.x;
    int e0 = blockIdx.x * BM;

    if (tid < 128) {
        int ge = e0 + tid;
        int r = 0, c = 0; float mk = 0.f;
        if (ge < E) { r = ei[ge]; c = ei[E + ge]; mk = edge_mask[ge]; }
        rs[tid] = r; cs[tid] = c; ms[tid] = mk;
        b2s[tid] = b2[tid];
    }
    if (tid < 160) {
        int i = tid >> 5, j = (tid & 31) * 4;
        *(float4*)(Ts + i * 128 + j) = *(const float4*)(W1 + (size_t)(256 + i) * HD + j);
    }
    stage_wt(Bs, wchunk + 2, tid);
    __syncthreads();

    {
        int e = tid & 127, jh = (tid >> 7) * 64;
        int ge = e0 + e;
        int gec = (ge < E) ? ge : 0;
        float rad = g_radial[gec];
        float4 ea = *(const float4*)(edge_attr + (size_t)gec * 4);
        const float* pa = g_Pa + (size_t)rs[e] * HD + jh;
        const float* pb = g_Pb + (size_t)cs[e] * HD + jh;
#pragma unroll 4
        for (int i = 0; i < 16; i++) {
            int j = i * 4;
            float4 va = *(const float4*)(pa + j);
            float4 vb = *(const float4*)(pb + j);
            float4 t0 = *(const float4*)(Ts + 0 * 128 + jh + j);
            float4 t1 = *(const float4*)(Ts + 1 * 128 + jh + j);
            float4 t2 = *(const float4*)(Ts + 2 * 128 + jh + j);
            float4 t3 = *(const float4*)(Ts + 3 * 128 + jh + j);
            float4 t4 = *(const float4*)(Ts + 4 * 128 + jh + j);
            float mx = va.x + vb.x + rad * t0.x + ea.x * t1.x + ea.y * t2.x + ea.z * t3.x + ea.w * t4.x;
            float my = va.y + vb.y + rad * t0.y + ea.x * t1.y + ea.y * t2.y + ea.z * t3.y + ea.w * t4.y;
            float mz = va.z + vb.z + rad * t0.z + ea.x * t1.z + ea.y * t2.z + ea.z * t3.z + ea.w * t4.z;
            float mw = va.w + vb.w + rad * t0.w + ea.x * t1.w + ea.y * t2.w + ea.z * t3.w + ea.w * t4.w;
            uint4 u = make_uint4(f2tf(silu_f(mx)), f2tf(silu_f(my)),
                                 f2tf(silu_f(mz)), f2tf(silu_f(mw)));
            *(uint4*)(As + e * S2 + jh + j) = u;
        }
    }
    __syncthreads();

    int lane = tid & 31, wid = tid >> 5;
    int g = lane >> 2, tg = lane & 3;
    int wm = wid & 1, wn = wid >> 1;

    float acc[4][4][4];
#pragma unroll
    for (int mt = 0; mt < 4; mt++)
#pragma unroll
        for (int nt = 0; nt < 4; nt++)
#pragma unroll
            for (int q = 0; q < 4; q++) acc[mt][nt][q] = 0.f;

#pragma unroll 1
    for (int kc = 0; kc < 16; kc++) {
        int kb = kc * 8;
        uint32_t a[4][4];
#pragma unroll
        for (int mt = 0; mt < 4; mt++) {
            int rr = wm * 64 + mt * 16 + g;
            a[mt][0] = As[rr * S2 + kb + tg];
            a[mt][1] = As[(rr + 8) * S2 + kb + tg];
            a[mt][2] = As[rr * S2 + kb + tg + 4];
            a[mt][3] = As[(rr + 8) * S2 + kb + tg + 4];
        }
#pragma unroll
        for (int nt = 0; nt < 4; nt++) {
            int cc = wn * 32 + nt * 8 + g;
            uint32_t b[2] = { Bs[cc * S2 + kb + tg], Bs[cc * S2 + kb + tg + 4] };
#pragma unroll
            for (int mt = 0; mt < 4; mt++) mma8(acc[mt][nt], a[mt], b);
        }
    }

#pragma unroll
    for (int mt = 0; mt < 4; mt++) {
#pragma unroll
        for (int nt = 0; nt < 4; nt++) {
            int col = wn * 32 + nt * 8 + 2 * tg;
            int r0 = wm * 64 + mt * 16 + g;
            int r1 = r0 + 8;
            float bb0 = b2s[col], bb1 = b2s[col + 1];
            if (e0 + r0 < E) {
                float mk = ms[r0];
                red_v2(&g_agg[rs[r0] * HD + col],
                       silu_f(acc[mt][nt][0] + bb0) * mk,
                       silu_f(acc[mt][nt][1] + bb1) * mk);
            }
            if (e0 + r1 < E) {
                float mk = ms[r1];
                red_v2(&g_agg[rs[r1] * HD + col],
                       silu_f(acc[mt][nt][2] + bb0) * mk,
                       silu_f(acc[mt][nt][3] + bb1) * mk);
            }
        }
    }
}

// ---------------------------------------------------------------------------
// Node model on tensor cores
// ---------------------------------------------------------------------------
#define NO_B1 0
#define NO_B2 512
#define NO_H0 1024
#define NO_TN 7168
#define NO_A  12800
#define NO_B  (12800 + 67584)
#define NODE_SMEM (12800 + 2 * 67584)

__global__ void __launch_bounds__(256, 1) node_mma_kernel(
    float* __restrict__ h, const float* __restrict__ h0,
    const float* __restrict__ W1, const float* __restrict__ b1,
    const float* __restrict__ b2, int wchunk, int N) {
    extern __shared__ char sm[];
    float*    b1s = (float*)(sm + NO_B1);
    float*    b2s = (float*)(sm + NO_B2);
    float*    h0s = (float*)(sm + NO_H0);   // [128][12]
    float*    Tn  = (float*)(sm + NO_TN);   // [11][128]
    uint32_t* As  = (uint32_t*)(sm + NO_A);
    uint32_t* Bs  = (uint32_t*)(sm + NO_B);

    int tid = threadIdx.x;
    int r0 = blockIdx.x * 128;
    if (tid < 128) { b1s[tid] = b1[tid]; b2s[tid] = b2[tid]; }
    {
        int row = tid & 127, half = tid >> 7;
        int gr = r0 + row; if (gr >= N) gr = N - 1;
        const float* src = h0 + (size_t)gr * 11;
#pragma unroll
        for (int q = 0; q < 6; q++) {
            int k = half * 6 + q;
            if (k < 11) h0s[row * 12 + k] = src[k];
        }
    }
    for (int idx = tid; idx < 11 * 32; idx += 256) {
        int i = idx >> 5, j = (idx & 31) * 4;
        *(float4*)(Tn + i * 128 + j) = *(const float4*)(W1 + (size_t)(256 + i) * HD + j);
    }

    int lane = tid & 31, wid = tid >> 5;
    int g = lane >> 2, tg = lane & 3;
    int wm = wid & 1, wn = wid >> 1;

    float acc[4][4][4];
#pragma unroll
    for (int mt = 0; mt < 4; mt++)
#pragma unroll
        for (int nt = 0; nt < 4; nt++)
#pragma unroll
            for (int q = 0; q < 4; q++) acc[mt][nt][q] = 0.f;

    for (int rep = 0; rep < 2; rep++) {
        __syncthreads();
        const float* src = rep ? g_agg : h;
        for (int idx = tid; idx < 4096; idx += 256) {
            int row = idx & 127, kg = idx >> 7;
            int gr = r0 + row; if (gr >= N) gr = N - 1;
            float4 v = *(const float4*)(src + (size_t)gr * HD + kg * 4);
            uint4 u = make_uint4(f2tf(v.x), f2tf(v.y), f2tf(v.z), f2tf(v.w));
            *(uint4*)(As + row * S2 + kg * 4) = u;
        }
        stage_wt(Bs, wchunk + 3 + rep, tid);
        __syncthreads();

#pragma unroll 1
        for (int kc = 0; kc < 16; kc++) {
            int kb = kc * 8;
            uint32_t a[4][4];
#pragma unroll
            for (int mt = 0; mt < 4; mt++) {
                int rr = wm * 64 + mt * 16 + g;
                a[mt][0] = As[rr * S2 + kb + tg];
                a[mt][1] = As[(rr + 8) * S2 + kb + tg];
                a[mt][2] = As[rr * S2 + kb + tg + 4];
                a[mt][3] = As[(rr + 8) * S2 + kb + tg + 4];
            }
#pragma unroll
            for (int nt = 0; nt < 4; nt++) {
                int cc = wn * 32 + nt * 8 + g;
                uint32_t b[2] = { Bs[cc * S2 + kb + tg], Bs[cc * S2 + kb + tg + 4] };
#pragma unroll
                for (int mt = 0; mt < 4; mt++) mma8(acc[mt][nt], a[mt], b);
            }
        }
    }
    __syncthreads();

#pragma unroll
    for (int mt = 0; mt < 4; mt++) {
        int rr = wm * 64 + mt * 16 + g;
#pragma unroll
        for (int nt = 0; nt < 4; nt++) {
            int col = wn * 32 + nt * 8 + 2 * tg;
            float v[4];
            v[0] = acc[mt][nt][0] + b1s[col];
            v[1] = acc[mt][nt][1] + b1s[col + 1];
            v[2] = acc[mt][nt][2] + b1s[col];
            v[3] = acc[mt][nt][3] + b1s[col + 1];
#pragma unroll
            for (int k = 0; k < 11; k++) {
                float t0 = Tn[k * 128 + col];
                float t1 = Tn[k * 128 + col + 1];
                float a0 = h0s[rr * 12 + k];
                float a1 = h0s[(rr + 8) * 12 + k];
                v[0] += a0 * t0; v[1] += a0 * t1;
                v[2] += a1 * t0; v[3] += a1 * t1;
            }
            As[rr * S2 + col]           = f2tf(silu_f(v[0]));
            As[rr * S2 + col + 1]       = f2tf(silu_f(v[1]));
            As[(rr + 8) * S2 + col]     = f2tf(silu_f(v[2]));
            As[(rr + 8) * S2 + col + 1] = f2tf(silu_f(v[3]));
        }
    }
    stage_wt(Bs, wchunk + 5, tid);
#pragma unroll
    for (int mt = 0; mt < 4; mt++)
#pragma unroll
        for (int nt = 0; nt < 4; nt++)
#pragma unroll
            for (int q = 0; q < 4; q++) acc[mt][nt][q] = 0.f;
    __syncthreads();

#pragma unroll 1
    for (int kc = 0; kc < 16; kc++) {
        int kb = kc * 8;
        uint32_t a[4][4];
#pragma unroll
        for (int mt = 0; mt < 4; mt++) {
            int rr = wm * 64 + mt * 16 + g;
            a[mt][0] = As[rr * S2 + kb + tg];
            a[mt][1] = As[(rr + 8) * S2 + kb + tg];
            a[mt][2] = As[rr * S2 + kb + tg + 4];
            a[mt][3] = As[(rr + 8) * S2 + kb + tg + 4];
        }
#pragma unroll
        for (int nt = 0; nt < 4; nt++) {
            int cc = wn * 32 + nt * 8 + g;
            uint32_t b[2] = { Bs[cc * S2 + kb + tg], Bs[cc * S2 + kb + tg + 4] };
#pragma unroll
            for (int mt = 0; mt < 4; mt++) mma8(acc[mt][nt], a[mt], b);
        }
    }

#pragma unroll
    for (int mt = 0; mt < 4; mt++) {
        int rr = wm * 64 + mt * 16 + g;
#pragma unroll
        for (int nt = 0; nt < 4; nt++) {
            int col = wn * 32 + nt * 8 + 2 * tg;
            float bb0 = b2s[col], bb1 = b2s[col + 1];
            if (r0 + rr < N) {
                float* p = h + (size_t)(r0 + rr) * HD + col;
                float2 old = *(float2*)p;
                *(float2*)p = make_float2(old.x + acc[mt][nt][0] + bb0,
                                          old.y + acc[mt][nt][1] + bb1);
            }
            if (r0 + rr + 8 < N) {
                float* p = h + (size_t)(r0 + rr + 8) * HD + col;
                float2 old = *(float2*)p;
                *(float2*)p = make_float2(old.x + acc[mt][nt][2] + bb0,
                                          old.y + acc[mt][nt][3] + bb1);
            }
        }
    }
}

// ---------------------------------------------------------------------------
extern "C" void kernel_launch(void* const* d_in, const int* in_sizes, int n_in,
                              void* d_out, int out_size) {
    const float* h0        = (const float*)d_in[0];
    const float* x         = (const float*)d_in[1];
    const int*   ei        = (const int*)  d_in[2];
    const float* edge_attr = (const float*)d_in[3];
    const float* edge_mask = (const float*)d_in[5];

    int wi = (in_sizes[6] == 1) ? 7 : 6;
    const float* emb_w = (const float*)d_in[wi + 0];
    const float* emb_b = (const float*)d_in[wi + 1];
    const float* ew1   = (const float*)d_in[wi + 2];
    const float* eb1   = (const float*)d_in[wi + 3];
    const float* ew2   = (const float*)d_in[wi + 4];
    const float* eb2   = (const float*)d_in[wi + 5];
    const float* nw1   = (const float*)d_in[wi + 6];
    const float* nb1   = (const float*)d_in[wi + 7];
    const float* nw2   = (const float*)d_in[wi + 8];
    const float* nb2   = (const float*)d_in[wi + 9];

    float* h = (float*)d_out;
    int N = in_sizes[0] / 11;
    int E = in_sizes[3] / 4;

    cudaFuncSetAttribute(proj_kernel,     cudaFuncAttributeMaxDynamicSharedMemorySize, PROJ_SMEM);
    cudaFuncSetAttribute(edge2_kernel,    cudaFuncAttributeMaxDynamicSharedMemorySize, EDGE_SMEM);
    cudaFuncSetAttribute(node_mma_kernel, cudaFuncAttributeMaxDynamicSharedMemorySize, NODE_SMEM);

    wtrans_kernel<<<dim3(64, 24), 256>>>(ew1, ew2, nw1, nw2);
    radial_kernel<<<(E + 255) / 256, 256>>>(x, ei, E);
    embed_kernel<<<N, HD>>>(h0, emb_w, emb_b, h);

    int n4 = (N * HD) / 4;
    int pblocks = (N + 127) / 128;
    int eblocks = (E + BM - 1) / BM;

    for (int l = 0; l < NL; l++) {
        proj_kernel<<<pblocks, 256, PROJ_SMEM>>>(h, eb1 + l * HD, l * 6, N);
        zero_agg_kernel<<<(n4 + 255) / 256, 256>>>(n4);
        edge2_kernel<<<eblocks, 256, EDGE_SMEM>>>(edge_attr, edge_mask, ei,
                                                  ew1 + (size_t)l * 261 * HD,
                                                  eb2 + l * HD, l * 6, E);
        node_mma_kernel<<<pblocks, 256, NODE_SMEM>>>(h, h0,
                                                     nw1 + (size_t)l * 267 * HD, nb1 + l * HD,
                                                     nb2 + l * HD, l * 6, N);
    }
}